// round 13
// baseline (speedup 1.0000x reference)
#include <cuda_runtime.h>
#include <cuda_bf16.h>
#include <cstdint>
#include <math.h>

#define Bsz  4
#define CIN  256
#define COUT 128
#define HW   4096

// ---------------- device scratch ----------------
__device__ float g_xt[Bsz * HW * CIN];        // NHWC x
__device__ float g_off[Bsz][27][HW];
__device__ float g_out1[Bsz][COUT][HW];
__device__ uint4 g_wAhi[16 * 18 * 8 * 32];    // deform A-fragments (tf32 hi)
__device__ uint4 g_wAlo[16 * 18 * 8 * 32];    // deform A-fragments (tf32 lo)
__device__ uint4 g_wBhi[4 * 8 * 8 * 8 * 32];  // transp A-fragments per parity (tf32 hi)
__device__ uint4 g_wBlo[4 * 8 * 8 * 8 * 32];  // transp A-fragments per parity (tf32 lo)
__device__ float g_bn1s[COUT], g_bn1b[COUT];
__device__ float g_bn2s[COUT], g_bn2b[COUT];
__device__ float g_psum[2][512][2];

__device__ __forceinline__ unsigned f2tf(float f) {
    unsigned u;
    asm("cvt.rna.tf32.f32 %0, %1;" : "=r"(u) : "f"(f));
    return u;
}

// ---------------- weight prep ----------------
__global__ void prep_kernel(const float* __restrict__ dcn_w,
                            const float* __restrict__ up_w) {
    int i = blockIdx.x * blockDim.x + threadIdx.x;
    if (i < 73728) {                       // deform: 16 cb * 18 kc * 8 wr * 32 lanes
        int lane = i & 31;
        int wr   = (i >> 5) & 7;
        int ck   = i >> 8;
        int kc   = ck % 18;
        int cb   = ck / 18;
        int g    = lane >> 2;
        int tig  = lane & 3;
        int row0 = wr * 16 + g,  row1 = row0 + 8;
        int col0 = kc * 8 + tig, col1 = col0 + 4;
        float w0 = dcn_w[row0 * 2304 + (cb * 16 + (col0 & 15)) * 9 + (col0 >> 4)];
        float w1 = dcn_w[row1 * 2304 + (cb * 16 + (col0 & 15)) * 9 + (col0 >> 4)];
        float w2 = dcn_w[row0 * 2304 + (cb * 16 + (col1 & 15)) * 9 + (col1 >> 4)];
        float w3 = dcn_w[row1 * 2304 + (cb * 16 + (col1 & 15)) * 9 + (col1 >> 4)];
        unsigned h0 = f2tf(w0), h1 = f2tf(w1), h2 = f2tf(w2), h3 = f2tf(w3);
        g_wAhi[i] = make_uint4(h0, h1, h2, h3);
        g_wAlo[i] = make_uint4(f2tf(w0 - __uint_as_float(h0)),
                               f2tf(w1 - __uint_as_float(h1)),
                               f2tf(w2 - __uint_as_float(h2)),
                               f2tf(w3 - __uint_as_float(h3)));
    }
    if (i < 65536) {                       // transp: 4 par * 8 cb * 8 kc * 8 wr * 32 lanes
        int lane = i & 31;
        int wr   = (i >> 5) & 7;
        int kc   = (i >> 8) & 7;
        int cb   = (i >> 11) & 7;
        int par  = i >> 14;
        int py = par >> 1, px = par & 1;
        int g = lane >> 2, tig = lane & 3;
        int row0 = wr * 16 + g, row1 = row0 + 8;
        int col0 = kc * 8 + tig, col1 = col0 + 4;
        auto wval = [&](int row, int col) -> float {
            int ci = col >> 2, ts = col & 3;
            int t = ts >> 1, s = ts & 1;
            int ch = cb * 16 + ci;
            int ky = py + 2 * t, kx = px + 2 * s;
            return up_w[((ch * 128 + row) * 4 + (3 - ky)) * 4 + (3 - kx)];
        };
        float w0 = wval(row0, col0), w1 = wval(row1, col0);
        float w2 = wval(row0, col1), w3 = wval(row1, col1);
        unsigned h0 = f2tf(w0), h1 = f2tf(w1), h2 = f2tf(w2), h3 = f2tf(w3);
        g_wBhi[i] = make_uint4(h0, h1, h2, h3);
        g_wBlo[i] = make_uint4(f2tf(w0 - __uint_as_float(h0)),
                               f2tf(w1 - __uint_as_float(h1)),
                               f2tf(w2 - __uint_as_float(h2)),
                               f2tf(w3 - __uint_as_float(h3)));
    }
}

// ---------------- NCHW -> NHWC transpose of x ----------------
__global__ void nhwc_kernel(const float* __restrict__ x) {
    __shared__ float t[32][33];
    int b  = blockIdx.z;
    int p0 = blockIdx.x * 32;
    int c0 = blockIdx.y * 32;
    int tx = threadIdx.x, ty = threadIdx.y;
#pragma unroll
    for (int i = 0; i < 4; i++)
        t[ty + i * 8][tx] = x[((size_t)(b * CIN + c0 + ty + i * 8)) * HW + p0 + tx];
    __syncthreads();
#pragma unroll
    for (int i = 0; i < 4; i++)
        g_xt[((size_t)(b * HW + p0 + ty + i * 8)) * CIN + c0 + tx] = t[tx][ty + i * 8];
}

// ---------------- offset conv: 3x3, 256 -> 27, pad 1 ----------------
#define OG 8
__global__ void offset_conv_kernel(const float* __restrict__ x,
                                   const float* __restrict__ off_w,
                                   const float* __restrict__ off_b) {
    int bh = blockIdx.x;
    int b = bh >> 6, h = bh & 63;
    int g = threadIdx.x >> 6;
    int w = threadIdx.x & 63;
    __shared__ float srow[OG][3][64];
    __shared__ float sws[OG][324];
    __shared__ float red[OG][64];

    float acc[27];
#pragma unroll
    for (int i = 0; i < 27; i++) acc[i] = 0.f;

    const float* xb = x + (size_t)b * CIN * HW;
    for (int cc = 0; cc < CIN / OG; cc++) {
        int c = g * (CIN / OG) + cc;
#pragma unroll
        for (int r = 0; r < 3; r++) {
            int hh = h + r - 1;
            srow[g][r][w] = (hh >= 0 && hh < 64) ? xb[(size_t)c * HW + hh * 64 + w] : 0.f;
        }
        const float* wc = off_w + c * 9;
        for (int j = w; j < 243; j += 64) {
            int oc = j / 9, tap = j - oc * 9;
            sws[g][oc * 12 + tap] = wc[(size_t)oc * (CIN * 9) + tap];
        }
        __syncthreads();
        float xv[9];
#pragma unroll
        for (int tap = 0; tap < 9; tap++) {
            int col = w + (tap % 3) - 1;
            xv[tap] = (col >= 0 && col < 64) ? srow[g][tap / 3][col] : 0.f;
        }
#pragma unroll
        for (int oc = 0; oc < 27; oc++) {
            const float4* wv = (const float4*)&sws[g][oc * 12];
            float4 w0 = wv[0], w1 = wv[1], w2 = wv[2];
            float a = acc[oc];
            a = fmaf(w0.x, xv[0], a); a = fmaf(w0.y, xv[1], a);
            a = fmaf(w0.z, xv[2], a); a = fmaf(w0.w, xv[3], a);
            a = fmaf(w1.x, xv[4], a); a = fmaf(w1.y, xv[5], a);
            a = fmaf(w1.z, xv[6], a); a = fmaf(w1.w, xv[7], a);
            a = fmaf(w2.x, xv[8], a);
            acc[oc] = a;
        }
        __syncthreads();
    }
    for (int oc = 0; oc < 27; oc++) {
        red[g][w] = acc[oc];
        __syncthreads();
        if (g == 0) {
            float v = red[0][w] + red[1][w] + red[2][w] + red[3][w]
                    + red[4][w] + red[5][w] + red[6][w] + red[7][w] + off_b[oc];
            if (oc >= 18) v = 1.f / (1.f + __expf(-v));
            g_off[b][oc][h * 64 + w] = v;
        }
        __syncthreads();
    }
}

// ---------------- deformable conv: gather(+tf32 split) + 3xTF32 mma.sync ----
// grid = B*128 (block = 32 px), block = 256. SINGLE-buffered u2 ssam -> 4 blocks/SM.
#define SSP2 36
#define SSAM_U2 (144 * SSP2)
#define DEF_SMEM (SSAM_U2 * 8 + 288 * 16 * 2)

#define MMA_TF32(d, a, b0, b1) \
    asm volatile("mma.sync.aligned.m16n8k8.row.col.f32.tf32.tf32.f32 " \
        "{%0,%1,%2,%3}, {%4,%5,%6,%7}, {%8,%9}, {%0,%1,%2,%3};" \
        : "+f"((d)[0]), "+f"((d)[1]), "+f"((d)[2]), "+f"((d)[3]) \
        : "r"((a).x), "r"((a).y), "r"((a).z), "r"((a).w), "r"(b0), "r"(b1))

__device__ __forceinline__ void dgather(int tid, int cb, uint2* sbuf,
                                        const float* __restrict__ xtb,
                                        const int4* sidx, const float4* swt) {
    for (int it = tid; it < 1152; it += 256) {
        int c = it & 15;
        int kp = it >> 4;
        int k = kp >> 3;
        int p4 = kp & 7;
        const float* xc = xtb + cb * 16 + c;
        uint2 o[4];
#pragma unroll
        for (int j = 0; j < 4; j++) {
            int e = k * 32 + p4 * 4 + j;
            int4 id = sidx[e];
            float4 wt = swt[e];
            float r =      wt.x * __ldg(xc + id.x * CIN);
            r = fmaf(wt.y, __ldg(xc + id.y * CIN), r);
            r = fmaf(wt.z, __ldg(xc + id.z * CIN), r);
            r = fmaf(wt.w, __ldg(xc + id.w * CIN), r);
            unsigned hi = f2tf(r);
            unsigned lo = f2tf(r - __uint_as_float(hi));
            o[j] = make_uint2(hi, lo);
        }
        uint2* dst = sbuf + (k * 16 + c) * SSP2 + p4 * 4;
        *(uint4*)(dst)     = *(const uint4*)&o[0];
        *(uint4*)(dst + 2) = *(const uint4*)&o[2];
    }
}

__global__ void __launch_bounds__(256) deform_kernel(const float* __restrict__ dcn_b) {
    extern __shared__ __align__(16) char dyn[];
    uint2* ssam  = (uint2*)dyn;
    int4*  sidx  = (int4*)(dyn + SSAM_U2 * 8);
    float4* swt  = (float4*)(dyn + SSAM_U2 * 8 + 288 * 16);

    int blk = blockIdx.x;
    int b = blk >> 7;
    int t = blk & 127;
    int h = t >> 1;
    int w0 = (t & 1) << 5;
    int p0 = h * 64 + w0;
    int tid = threadIdx.x;
    int lane = tid & 31, wid = tid >> 5;

    for (int e = tid; e < 288; e += 256) {
        int k = e >> 5, p = e & 31;
        float dy = g_off[b][k][p0 + p];
        float dx = g_off[b][9 + k][p0 + p];
        float m  = g_off[b][18 + k][p0 + p];
        float py = dy + (float)(k / 3 - 1 + h);
        float px = dx + (float)(k % 3 - 1 + w0 + p);
        float y0f = floorf(py), x0f = floorf(px);
        int y0 = (int)y0f, x0i = (int)x0f;
        float wy = py - y0f, wx = px - x0f;
        float w00 = (1.f - wy) * (1.f - wx) * m;
        float w01 = (1.f - wy) * wx * m;
        float w10 = wy * (1.f - wx) * m;
        float w11 = wy * wx * m;
        int y1 = y0 + 1, x1i = x0i + 1;
        bool y0v = (unsigned)y0  < 64u, y1v = (unsigned)y1  < 64u;
        bool x0v = (unsigned)x0i < 64u, x1v = (unsigned)x1i < 64u;
        int y0c = min(max(y0, 0), 63),  y1c = min(max(y1, 0), 63);
        int x0c = min(max(x0i, 0), 63), x1c = min(max(x1i, 0), 63);
        sidx[e] = make_int4(y0c * 64 + x0c, y0c * 64 + x1c,
                            y1c * 64 + x0c, y1c * 64 + x1c);
        swt[e] = make_float4(y0v && x0v ? w00 : 0.f,
                             y0v && x1v ? w01 : 0.f,
                             y1v && x0v ? w10 : 0.f,
                             y1v && x1v ? w11 : 0.f);
    }
    __syncthreads();

    int g   = lane >> 2;
    int tig = lane & 3;

    float d[4][4];
#pragma unroll
    for (int i = 0; i < 4; i++)
#pragma unroll
        for (int j = 0; j < 4; j++) d[i][j] = 0.f;

    unsigned sbase = (unsigned)__cvta_generic_to_shared(ssam);
    const float* xtb = g_xt + (size_t)b * HW * CIN;

#pragma unroll 1
    for (int cb = 0; cb < 16; cb++) {
        dgather(tid, cb, ssam, xtb, sidx, swt);
        __syncthreads();
        const uint4* ph = g_wAhi + ((cb * 18) * 8 + wid) * 32 + lane;
        const uint4* pl = g_wAlo + ((cb * 18) * 8 + wid) * 32 + lane;
#pragma unroll 2
        for (int kc = 0; kc < 18; kc++) {
            uint4 ah = __ldg(ph + kc * 256);
            uint4 al = __ldg(pl + kc * 256);
            unsigned base0 = sbase + ((kc * 8 + tig) * SSP2 + g) * 8;
            unsigned base1 = base0 + 4 * SSP2 * 8;
#pragma unroll
            for (int nt = 0; nt < 4; nt++) {
                unsigned h0, l0, h1, l1;
                asm volatile("ld.shared.v2.u32 {%0,%1}, [%2];"
                             : "=r"(h0), "=r"(l0) : "r"(base0 + nt * 64));
                asm volatile("ld.shared.v2.u32 {%0,%1}, [%2];"
                             : "=r"(h1), "=r"(l1) : "r"(base1 + nt * 64));
                MMA_TF32(d[nt], ah, h0, h1);
                MMA_TF32(d[nt], al, h0, h1);
                MMA_TF32(d[nt], ah, l0, l1);
            }
        }
        __syncthreads();
    }

    int oc0 = wid * 16 + g;
    float bias0 = dcn_b[oc0], bias1 = dcn_b[oc0 + 8];
    float* r0 = &g_out1[b][oc0][p0];
    float* r1 = &g_out1[b][oc0 + 8][p0];
#pragma unroll
    for (int nt = 0; nt < 4; nt++) {
        int col = nt * 8 + 2 * tig;
        *(float2*)(r0 + col) = make_float2(d[nt][0] + bias0, d[nt][1] + bias0);
        *(float2*)(r1 + col) = make_float2(d[nt][2] + bias1, d[nt][3] + bias1);
    }
}

// ---------------- BN stats ----------------
__global__ void bn_partial_kernel(const float* __restrict__ ext, int which) {
    int bx = blockIdx.x;
    int c = bx >> 2, b = bx & 3;
    const float* plane = which ? ext + (size_t)(b * 128 + c) * 16384
                               : &g_out1[b][c][0];
    int n4 = which ? 4096 : 1024;
    float s = 0.f, s2 = 0.f;
    const float4* p4 = (const float4*)plane;
    for (int i = threadIdx.x; i < n4; i += 128) {
        float4 v = p4[i];
        s  += v.x + v.y + v.z + v.w;
        s2 += v.x*v.x + v.y*v.y + v.z*v.z + v.w*v.w;
    }
    __shared__ float rs[128], rq[128];
    rs[threadIdx.x] = s; rq[threadIdx.x] = s2;
    __syncthreads();
    for (int st = 64; st > 0; st >>= 1) {
        if (threadIdx.x < st) {
            rs[threadIdx.x] += rs[threadIdx.x + st];
            rq[threadIdx.x] += rq[threadIdx.x + st];
        }
        __syncthreads();
    }
    if (threadIdx.x == 0) {
        g_psum[which][bx][0] = rs[0];
        g_psum[which][bx][1] = rq[0];
    }
}

__global__ void bn_final_kernel(const float* __restrict__ gamma,
                                const float* __restrict__ beta, int which) {
    int c = threadIdx.x;
    float s = 0.f, s2 = 0.f;
#pragma unroll
    for (int b = 0; b < 4; b++) {
        s  += g_psum[which][c * 4 + b][0];
        s2 += g_psum[which][c * 4 + b][1];
    }
    float n  = which ? 65536.f : 16384.f;
    float mu = s / n;
    float var = s2 / n - mu * mu;
    float sc = gamma[c] * rsqrtf(var + 1e-5f);
    float sh = beta[c] - mu * sc;
    if (which == 0) { g_bn1s[c] = sc; g_bn1b[c] = sh; }
    else            { g_bn2s[c] = sc; g_bn2b[c] = sh; }
}

// ---------------- transposed conv via 3xTF32 mma.sync (u2 hi/lo ssam) -------
#define SSP 68
__global__ void __launch_bounds__(256) transp_kernel(float* __restrict__ out) {
    int blk = blockIdx.x;
    int u   = blk & 63;
    int par = (blk >> 6) & 3;
    int b   = blk >> 8;
    int py = par >> 1, px = par & 1;
    int tid = threadIdx.x;
    int lane = tid & 31, wid = tid >> 5;

    __shared__ float srow[16 * 2 * 64];
    __shared__ __align__(16) uint2 ssam[64 * SSP];

    int g = lane >> 2, tig = lane & 3;

    float d[8][4];
#pragma unroll
    for (int i = 0; i < 8; i++)
#pragma unroll
        for (int j = 0; j < 4; j++) d[i][j] = 0.f;

    unsigned sbase = (unsigned)__cvta_generic_to_shared(ssam);

#pragma unroll 1
    for (int cb = 0; cb < 8; cb++) {
        // stage with fused BN1 + ReLU
        for (int e = tid; e < 512; e += 256) {
            int ci = e >> 5;
            int tt = (e >> 4) & 1;
            int f4 = e & 15;
            int c  = cb * 16 + ci;
            int row = u + py - 1 + tt;
            float4 v = make_float4(0.f, 0.f, 0.f, 0.f);
            if ((unsigned)row < 64u) {
                float4 r = *(const float4*)&g_out1[b][c][row * 64 + f4 * 4];
                float sc = g_bn1s[c], sh = g_bn1b[c];
                v.x = fmaxf(fmaf(r.x, sc, sh), 0.f);
                v.y = fmaxf(fmaf(r.y, sc, sh), 0.f);
                v.z = fmaxf(fmaf(r.z, sc, sh), 0.f);
                v.w = fmaxf(fmaf(r.w, sc, sh), 0.f);
            }
            *(float4*)&srow[(ci * 2 + tt) * 64 + f4 * 4] = v;
        }
        __syncthreads();
        // expand to ssam[ck][p] with column shift, hi/lo split done HERE (once)
        for (int e = tid; e < 4096; e += 256) {
            int ck = e >> 6;
            int p  = e & 63;
            int ci = ck >> 2;
            int tt = (ck >> 1) & 1;
            int s  = ck & 1;
            int col = p + px - 1 + s;
            float v = (col >= 0 && col < 64) ? srow[(ci * 2 + tt) * 64 + col] : 0.f;
            unsigned hi = f2tf(v);
            unsigned lo = f2tf(v - __uint_as_float(hi));
            ssam[ck * SSP + p] = make_uint2(hi, lo);
        }
        __syncthreads();
        // GEMM over 64 ck (8 k-frags)
        const uint4* ph = g_wBhi + (((par * 8 + cb) * 8) * 8 + wid) * 32 + lane;
        const uint4* pl = g_wBlo + (((par * 8 + cb) * 8) * 8 + wid) * 32 + lane;
#pragma unroll 2
        for (int kc = 0; kc < 8; kc++) {
            uint4 ah = __ldg(ph + kc * 256);
            uint4 al = __ldg(pl + kc * 256);
            unsigned base0 = sbase + ((kc * 8 + tig) * SSP + g) * 8;
            unsigned base1 = base0 + 4 * SSP * 8;
#pragma unroll
            for (int nt = 0; nt < 8; nt++) {
                unsigned h0, l0, h1, l1;
                asm volatile("ld.shared.v2.u32 {%0,%1}, [%2];"
                             : "=r"(h0), "=r"(l0) : "r"(base0 + nt * 64));
                asm volatile("ld.shared.v2.u32 {%0,%1}, [%2];"
                             : "=r"(h1), "=r"(l1) : "r"(base1 + nt * 64));
                MMA_TF32(d[nt], ah, h0, h1);
                MMA_TF32(d[nt], al, h0, h1);
                MMA_TF32(d[nt], ah, l0, l1);
            }
        }
        __syncthreads();
    }

    int y = 2 * u + py;
    int oc0 = wid * 16 + g;
    float* r0 = out + (((size_t)(b * 128 + oc0)     * 128 + y) * 128) + px;
    float* r1 = out + (((size_t)(b * 128 + oc0 + 8) * 128 + y) * 128) + px;
#pragma unroll
    for (int nt = 0; nt < 8; nt++) {
        int p = nt * 8 + 2 * tig;
        r0[2 * p]       = d[nt][0];
        r0[2 * (p + 1)] = d[nt][1];
        r1[2 * p]       = d[nt][2];
        r1[2 * (p + 1)] = d[nt][3];
    }
}

// ---------------- BN2 apply + ReLU ----------------
__global__ void bn_apply_kernel(float* __restrict__ out) {
    int i = blockIdx.x * 256 + threadIdx.x;
    int c = (i >> 12) & 127;
    float sc = g_bn2s[c], sh = g_bn2b[c];
    float4 v = ((float4*)out)[i];
    v.x = fmaxf(v.x * sc + sh, 0.f);
    v.y = fmaxf(v.y * sc + sh, 0.f);
    v.z = fmaxf(v.z * sc + sh, 0.f);
    v.w = fmaxf(v.w * sc + sh, 0.f);
    ((float4*)out)[i] = v;
}

// ---------------- launch ----------------
extern "C" void kernel_launch(void* const* d_in, const int* in_sizes, int n_in,
                              void* d_out, int out_size) {
    const float* x     = (const float*)d_in[0];
    const float* off_w = (const float*)d_in[1];
    const float* off_b = (const float*)d_in[2];
    const float* dcn_w = (const float*)d_in[3];
    const float* dcn_b = (const float*)d_in[4];
    const float* bn1_g = (const float*)d_in[5];
    const float* bn1_b = (const float*)d_in[6];
    const float* up_w  = (const float*)d_in[7];
    const float* bn2_g = (const float*)d_in[8];
    const float* bn2_b = (const float*)d_in[9];
    float* out = (float*)d_out;

    cudaFuncSetAttribute(deform_kernel,
                         cudaFuncAttributeMaxDynamicSharedMemorySize, DEF_SMEM);

    prep_kernel<<<288, 256>>>(dcn_w, up_w);
    nhwc_kernel<<<dim3(128, 8, 4), dim3(32, 8)>>>(x);
    offset_conv_kernel<<<256, 512>>>(x, off_w, off_b);
    deform_kernel<<<512, 256, DEF_SMEM>>>(dcn_b);
    bn_partial_kernel<<<512, 128>>>(nullptr, 0);
    bn_final_kernel<<<1, 128>>>(bn1_g, bn1_b, 0);
    transp_kernel<<<1024, 256>>>(out);
    bn_partial_kernel<<<512, 128>>>(out, 1);
    bn_final_kernel<<<1, 128>>>(bn2_g, bn2_b, 1);
    bn_apply_kernel<<<8192, 256>>>(out);
}

// round 14
// speedup vs baseline: 1.0254x; 1.0254x over previous
#include <cuda_runtime.h>
#include <cuda_bf16.h>
#include <cstdint>
#include <math.h>

#define Bsz  4
#define CIN  256
#define COUT 128
#define HW   4096

// ---------------- device scratch ----------------
__device__ float g_xt[Bsz * HW * CIN];        // NHWC x
__device__ float g_off[Bsz][27][HW];
__device__ float g_out1[Bsz][COUT][HW];
__device__ uint4 g_wAhi[16 * 18 * 8 * 32];    // deform A-fragments (tf32 hi)
__device__ uint4 g_wAlo[16 * 18 * 8 * 32];    // deform A-fragments (tf32 lo)
__device__ uint4 g_wBhi[4 * 8 * 8 * 8 * 32];  // transp A-fragments per parity (tf32 hi)
__device__ uint4 g_wBlo[4 * 8 * 8 * 8 * 32];  // transp A-fragments per parity (tf32 lo)
__device__ float g_bn1s[COUT], g_bn1b[COUT];
__device__ float g_bn2s[COUT], g_bn2b[COUT];
__device__ float g_psum[2][512][2];

__device__ __forceinline__ unsigned f2tf(float f) {
    unsigned u;
    asm("cvt.rna.tf32.f32 %0, %1;" : "=r"(u) : "f"(f));
    return u;
}

// ---------------- weight prep ----------------
__global__ void prep_kernel(const float* __restrict__ dcn_w,
                            const float* __restrict__ up_w) {
    int i = blockIdx.x * blockDim.x + threadIdx.x;
    if (i < 73728) {                       // deform: 16 cb * 18 kc * 8 wr * 32 lanes
        int lane = i & 31;
        int wr   = (i >> 5) & 7;
        int ck   = i >> 8;
        int kc   = ck % 18;
        int cb   = ck / 18;
        int g    = lane >> 2;
        int tig  = lane & 3;
        int row0 = wr * 16 + g,  row1 = row0 + 8;
        int col0 = kc * 8 + tig, col1 = col0 + 4;
        float w0 = dcn_w[row0 * 2304 + (cb * 16 + (col0 & 15)) * 9 + (col0 >> 4)];
        float w1 = dcn_w[row1 * 2304 + (cb * 16 + (col0 & 15)) * 9 + (col0 >> 4)];
        float w2 = dcn_w[row0 * 2304 + (cb * 16 + (col1 & 15)) * 9 + (col1 >> 4)];
        float w3 = dcn_w[row1 * 2304 + (cb * 16 + (col1 & 15)) * 9 + (col1 >> 4)];
        unsigned h0 = f2tf(w0), h1 = f2tf(w1), h2 = f2tf(w2), h3 = f2tf(w3);
        g_wAhi[i] = make_uint4(h0, h1, h2, h3);
        g_wAlo[i] = make_uint4(f2tf(w0 - __uint_as_float(h0)),
                               f2tf(w1 - __uint_as_float(h1)),
                               f2tf(w2 - __uint_as_float(h2)),
                               f2tf(w3 - __uint_as_float(h3)));
    }
    if (i < 65536) {                       // transp: 4 par * 8 cb * 8 kc * 8 wr * 32 lanes
        int lane = i & 31;
        int wr   = (i >> 5) & 7;
        int kc   = (i >> 8) & 7;
        int cb   = (i >> 11) & 7;
        int par  = i >> 14;
        int py = par >> 1, px = par & 1;
        int g = lane >> 2, tig = lane & 3;
        int row0 = wr * 16 + g, row1 = row0 + 8;
        int col0 = kc * 8 + tig, col1 = col0 + 4;
        auto wval = [&](int row, int col) -> float {
            int ci = col >> 2, ts = col & 3;
            int t = ts >> 1, s = ts & 1;
            int ch = cb * 16 + ci;
            int ky = py + 2 * t, kx = px + 2 * s;
            return up_w[((ch * 128 + row) * 4 + (3 - ky)) * 4 + (3 - kx)];
        };
        float w0 = wval(row0, col0), w1 = wval(row1, col0);
        float w2 = wval(row0, col1), w3 = wval(row1, col1);
        unsigned h0 = f2tf(w0), h1 = f2tf(w1), h2 = f2tf(w2), h3 = f2tf(w3);
        g_wBhi[i] = make_uint4(h0, h1, h2, h3);
        g_wBlo[i] = make_uint4(f2tf(w0 - __uint_as_float(h0)),
                               f2tf(w1 - __uint_as_float(h1)),
                               f2tf(w2 - __uint_as_float(h2)),
                               f2tf(w3 - __uint_as_float(h3)));
    }
}

// ---------------- NCHW -> NHWC transpose of x ----------------
__global__ void nhwc_kernel(const float* __restrict__ x) {
    __shared__ float t[32][33];
    int b  = blockIdx.z;
    int p0 = blockIdx.x * 32;
    int c0 = blockIdx.y * 32;
    int tx = threadIdx.x, ty = threadIdx.y;
#pragma unroll
    for (int i = 0; i < 4; i++)
        t[ty + i * 8][tx] = x[((size_t)(b * CIN + c0 + ty + i * 8)) * HW + p0 + tx];
    __syncthreads();
#pragma unroll
    for (int i = 0; i < 4; i++)
        g_xt[((size_t)(b * HW + p0 + ty + i * 8)) * CIN + c0 + tx] = t[tx][ty + i * 8];
}

// ---------------- offset conv: 3x3, 256 -> 27, pad 1 ----------------
#define OG 8
__global__ void offset_conv_kernel(const float* __restrict__ x,
                                   const float* __restrict__ off_w,
                                   const float* __restrict__ off_b) {
    int bh = blockIdx.x;
    int b = bh >> 6, h = bh & 63;
    int g = threadIdx.x >> 6;
    int w = threadIdx.x & 63;
    __shared__ float srow[OG][3][64];
    __shared__ float sws[OG][324];
    __shared__ float red[OG][64];

    float acc[27];
#pragma unroll
    for (int i = 0; i < 27; i++) acc[i] = 0.f;

    const float* xb = x + (size_t)b * CIN * HW;
    for (int cc = 0; cc < CIN / OG; cc++) {
        int c = g * (CIN / OG) + cc;
#pragma unroll
        for (int r = 0; r < 3; r++) {
            int hh = h + r - 1;
            srow[g][r][w] = (hh >= 0 && hh < 64) ? xb[(size_t)c * HW + hh * 64 + w] : 0.f;
        }
        const float* wc = off_w + c * 9;
        for (int j = w; j < 243; j += 64) {
            int oc = j / 9, tap = j - oc * 9;
            sws[g][oc * 12 + tap] = wc[(size_t)oc * (CIN * 9) + tap];
        }
        __syncthreads();
        float xv[9];
#pragma unroll
        for (int tap = 0; tap < 9; tap++) {
            int col = w + (tap % 3) - 1;
            xv[tap] = (col >= 0 && col < 64) ? srow[g][tap / 3][col] : 0.f;
        }
#pragma unroll
        for (int oc = 0; oc < 27; oc++) {
            const float4* wv = (const float4*)&sws[g][oc * 12];
            float4 w0 = wv[0], w1 = wv[1], w2 = wv[2];
            float a = acc[oc];
            a = fmaf(w0.x, xv[0], a); a = fmaf(w0.y, xv[1], a);
            a = fmaf(w0.z, xv[2], a); a = fmaf(w0.w, xv[3], a);
            a = fmaf(w1.x, xv[4], a); a = fmaf(w1.y, xv[5], a);
            a = fmaf(w1.z, xv[6], a); a = fmaf(w1.w, xv[7], a);
            a = fmaf(w2.x, xv[8], a);
            acc[oc] = a;
        }
        __syncthreads();
    }
    for (int oc = 0; oc < 27; oc++) {
        red[g][w] = acc[oc];
        __syncthreads();
        if (g == 0) {
            float v = red[0][w] + red[1][w] + red[2][w] + red[3][w]
                    + red[4][w] + red[5][w] + red[6][w] + red[7][w] + off_b[oc];
            if (oc >= 18) v = 1.f / (1.f + __expf(-v));
            g_off[b][oc][h * 64 + w] = v;
        }
        __syncthreads();
    }
}

// ---------------- deformable conv (R10/R11 exact: db fp32 ssam + cvt in loop)
#define SSP2 36
__device__ __forceinline__ void dgather(int tid, int cb, float* sbuf,
                                        const float* __restrict__ xtb,
                                        const int4* sidx, const float4* swt) {
    for (int it = tid; it < 1152; it += 256) {
        int c = it & 15;
        int kp = it >> 4;
        int k = kp >> 3;
        int p4 = kp & 7;
        const float* xc = xtb + cb * 16 + c;
        float4 v;
        float* vp = &v.x;
#pragma unroll
        for (int j = 0; j < 4; j++) {
            int e = k * 32 + p4 * 4 + j;
            int4 id = sidx[e];
            float4 wt = swt[e];
            float r =      wt.x * __ldg(xc + id.x * CIN);
            r = fmaf(wt.y, __ldg(xc + id.y * CIN), r);
            r = fmaf(wt.z, __ldg(xc + id.z * CIN), r);
            r = fmaf(wt.w, __ldg(xc + id.w * CIN), r);
            vp[j] = r;
        }
        *(float4*)&sbuf[(k * 16 + c) * SSP2 + p4 * 4] = v;
    }
}

#define MMA_TF32(d, a, b0, b1) \
    asm volatile("mma.sync.aligned.m16n8k8.row.col.f32.tf32.tf32.f32 " \
        "{%0,%1,%2,%3}, {%4,%5,%6,%7}, {%8,%9}, {%0,%1,%2,%3};" \
        : "+f"((d)[0]), "+f"((d)[1]), "+f"((d)[2]), "+f"((d)[3]) \
        : "r"((a).x), "r"((a).y), "r"((a).z), "r"((a).w), "r"(b0), "r"(b1))

__global__ void __launch_bounds__(256) deform_kernel(const float* __restrict__ dcn_b) {
    int blk = blockIdx.x;
    int b = blk >> 7;
    int t = blk & 127;
    int h = t >> 1;
    int w0 = (t & 1) << 5;
    int p0 = h * 64 + w0;
    int tid = threadIdx.x;
    int lane = tid & 31, wid = tid >> 5;

    __shared__ int4  sidx[288];
    __shared__ float4 swt[288];
    __shared__ __align__(16) float ssam[2][144 * SSP2];

    for (int e = tid; e < 288; e += 256) {
        int k = e >> 5, p = e & 31;
        float dy = g_off[b][k][p0 + p];
        float dx = g_off[b][9 + k][p0 + p];
        float m  = g_off[b][18 + k][p0 + p];
        float py = dy + (float)(k / 3 - 1 + h);
        float px = dx + (float)(k % 3 - 1 + w0 + p);
        float y0f = floorf(py), x0f = floorf(px);
        int y0 = (int)y0f, x0i = (int)x0f;
        float wy = py - y0f, wx = px - x0f;
        float w00 = (1.f - wy) * (1.f - wx) * m;
        float w01 = (1.f - wy) * wx * m;
        float w10 = wy * (1.f - wx) * m;
        float w11 = wy * wx * m;
        int y1 = y0 + 1, x1i = x0i + 1;
        bool y0v = (unsigned)y0  < 64u, y1v = (unsigned)y1  < 64u;
        bool x0v = (unsigned)x0i < 64u, x1v = (unsigned)x1i < 64u;
        int y0c = min(max(y0, 0), 63),  y1c = min(max(y1, 0), 63);
        int x0c = min(max(x0i, 0), 63), x1c = min(max(x1i, 0), 63);
        sidx[e] = make_int4(y0c * 64 + x0c, y0c * 64 + x1c,
                            y1c * 64 + x0c, y1c * 64 + x1c);
        swt[e] = make_float4(y0v && x0v ? w00 : 0.f,
                             y0v && x1v ? w01 : 0.f,
                             y1v && x0v ? w10 : 0.f,
                             y1v && x1v ? w11 : 0.f);
    }
    __syncthreads();

    int g   = lane >> 2;
    int tig = lane & 3;

    float d[4][4];
#pragma unroll
    for (int i = 0; i < 4; i++)
#pragma unroll
        for (int j = 0; j < 4; j++) d[i][j] = 0.f;

    unsigned sbase = (unsigned)__cvta_generic_to_shared(&ssam[0][0]);
    const float* xtb = g_xt + (size_t)b * HW * CIN;

    dgather(tid, 0, &ssam[0][0], xtb, sidx, swt);
    __syncthreads();

#pragma unroll 1
    for (int cb = 0; cb < 16; cb++) {
        if (cb < 15) dgather(tid, cb + 1, &ssam[(cb + 1) & 1][0], xtb, sidx, swt);
        const uint4* ph = g_wAhi + ((cb * 18) * 8 + wid) * 32 + lane;
        const uint4* pl = g_wAlo + ((cb * 18) * 8 + wid) * 32 + lane;
        unsigned sb = sbase + (cb & 1) * (144 * SSP2 * 4);
#pragma unroll 2
        for (int kc = 0; kc < 18; kc++) {
            uint4 ah = __ldg(ph + kc * 256);
            uint4 al = __ldg(pl + kc * 256);
            unsigned base0 = sb + ((kc * 8 + tig) * SSP2 + g) * 4;
            unsigned base1 = base0 + 4 * SSP2 * 4;
#pragma unroll
            for (int nt = 0; nt < 4; nt++) {
                float s0, s1;
                asm volatile("ld.shared.f32 %0, [%1];" : "=f"(s0) : "r"(base0 + nt * 32));
                asm volatile("ld.shared.f32 %0, [%1];" : "=f"(s1) : "r"(base1 + nt * 32));
                unsigned bh0 = f2tf(s0), bh1 = f2tf(s1);
                unsigned bl0 = f2tf(s0 - __uint_as_float(bh0));
                unsigned bl1 = f2tf(s1 - __uint_as_float(bh1));
                MMA_TF32(d[nt], ah, bh0, bh1);
                MMA_TF32(d[nt], al, bh0, bh1);
                MMA_TF32(d[nt], ah, bl0, bl1);
            }
        }
        __syncthreads();
    }

    int oc0 = wid * 16 + g;
    float bias0 = dcn_b[oc0], bias1 = dcn_b[oc0 + 8];
    float* r0 = &g_out1[b][oc0][p0];
    float* r1 = &g_out1[b][oc0 + 8][p0];
#pragma unroll
    for (int nt = 0; nt < 4; nt++) {
        int col = nt * 8 + 2 * tig;
        *(float2*)(r0 + col) = make_float2(d[nt][0] + bias0, d[nt][1] + bias0);
        *(float2*)(r1 + col) = make_float2(d[nt][2] + bias1, d[nt][3] + bias1);
    }
}

// ---------------- BN stats ----------------
__global__ void bn_partial_kernel(const float* __restrict__ ext, int which) {
    int bx = blockIdx.x;
    int c = bx >> 2, b = bx & 3;
    const float* plane = which ? ext + (size_t)(b * 128 + c) * 16384
                               : &g_out1[b][c][0];
    int n4 = which ? 4096 : 1024;
    float s = 0.f, s2 = 0.f;
    const float4* p4 = (const float4*)plane;
    for (int i = threadIdx.x; i < n4; i += 128) {
        float4 v = p4[i];
        s  += v.x + v.y + v.z + v.w;
        s2 += v.x*v.x + v.y*v.y + v.z*v.z + v.w*v.w;
    }
    __shared__ float rs[128], rq[128];
    rs[threadIdx.x] = s; rq[threadIdx.x] = s2;
    __syncthreads();
    for (int st = 64; st > 0; st >>= 1) {
        if (threadIdx.x < st) {
            rs[threadIdx.x] += rs[threadIdx.x + st];
            rq[threadIdx.x] += rq[threadIdx.x + st];
        }
        __syncthreads();
    }
    if (threadIdx.x == 0) {
        g_psum[which][bx][0] = rs[0];
        g_psum[which][bx][1] = rq[0];
    }
}

__global__ void bn_final_kernel(const float* __restrict__ gamma,
                                const float* __restrict__ beta, int which) {
    int c = threadIdx.x;
    float s = 0.f, s2 = 0.f;
#pragma unroll
    for (int b = 0; b < 4; b++) {
        s  += g_psum[which][c * 4 + b][0];
        s2 += g_psum[which][c * 4 + b][1];
    }
    float n  = which ? 65536.f : 16384.f;
    float mu = s / n;
    float var = s2 / n - mu * mu;
    float sc = gamma[c] * rsqrtf(var + 1e-5f);
    float sh = beta[c] - mu * sc;
    if (which == 0) { g_bn1s[c] = sc; g_bn1b[c] = sh; }
    else            { g_bn2s[c] = sc; g_bn2b[c] = sh; }
}

// ---------------- transposed conv via 3xTF32 mma.sync (u2 hi/lo ssam, R13) --
#define SSP 68
__global__ void __launch_bounds__(256) transp_kernel(float* __restrict__ out) {
    int blk = blockIdx.x;
    int u   = blk & 63;
    int par = (blk >> 6) & 3;
    int b   = blk >> 8;
    int py = par >> 1, px = par & 1;
    int tid = threadIdx.x;
    int lane = tid & 31, wid = tid >> 5;

    __shared__ float srow[16 * 2 * 64];
    __shared__ __align__(16) uint2 ssam[64 * SSP];

    int g = lane >> 2, tig = lane & 3;

    float d[8][4];
#pragma unroll
    for (int i = 0; i < 8; i++)
#pragma unroll
        for (int j = 0; j < 4; j++) d[i][j] = 0.f;

    unsigned sbase = (unsigned)__cvta_generic_to_shared(ssam);

#pragma unroll 1
    for (int cb = 0; cb < 8; cb++) {
        for (int e = tid; e < 512; e += 256) {
            int ci = e >> 5;
            int tt = (e >> 4) & 1;
            int f4 = e & 15;
            int c  = cb * 16 + ci;
            int row = u + py - 1 + tt;
            float4 v = make_float4(0.f, 0.f, 0.f, 0.f);
            if ((unsigned)row < 64u) {
                float4 r = *(const float4*)&g_out1[b][c][row * 64 + f4 * 4];
                float sc = g_bn1s[c], sh = g_bn1b[c];
                v.x = fmaxf(fmaf(r.x, sc, sh), 0.f);
                v.y = fmaxf(fmaf(r.y, sc, sh), 0.f);
                v.z = fmaxf(fmaf(r.z, sc, sh), 0.f);
                v.w = fmaxf(fmaf(r.w, sc, sh), 0.f);
            }
            *(float4*)&srow[(ci * 2 + tt) * 64 + f4 * 4] = v;
        }
        __syncthreads();
        for (int e = tid; e < 4096; e += 256) {
            int ck = e >> 6;
            int p  = e & 63;
            int ci = ck >> 2;
            int tt = (ck >> 1) & 1;
            int s  = ck & 1;
            int col = p + px - 1 + s;
            float v = (col >= 0 && col < 64) ? srow[(ci * 2 + tt) * 64 + col] : 0.f;
            unsigned hi = f2tf(v);
            unsigned lo = f2tf(v - __uint_as_float(hi));
            ssam[ck * SSP + p] = make_uint2(hi, lo);
        }
        __syncthreads();
        const uint4* ph = g_wBhi + (((par * 8 + cb) * 8) * 8 + wid) * 32 + lane;
        const uint4* pl = g_wBlo + (((par * 8 + cb) * 8) * 8 + wid) * 32 + lane;
#pragma unroll 2
        for (int kc = 0; kc < 8; kc++) {
            uint4 ah = __ldg(ph + kc * 256);
            uint4 al = __ldg(pl + kc * 256);
            unsigned base0 = sbase + ((kc * 8 + tig) * SSP + g) * 8;
            unsigned base1 = base0 + 4 * SSP * 8;
#pragma unroll
            for (int nt = 0; nt < 8; nt++) {
                unsigned h0, l0, h1, l1;
                asm volatile("ld.shared.v2.u32 {%0,%1}, [%2];"
                             : "=r"(h0), "=r"(l0) : "r"(base0 + nt * 64));
                asm volatile("ld.shared.v2.u32 {%0,%1}, [%2];"
                             : "=r"(h1), "=r"(l1) : "r"(base1 + nt * 64));
                MMA_TF32(d[nt], ah, h0, h1);
                MMA_TF32(d[nt], al, h0, h1);
                MMA_TF32(d[nt], ah, l0, l1);
            }
        }
        __syncthreads();
    }

    int y = 2 * u + py;
    int oc0 = wid * 16 + g;
    float* r0 = out + (((size_t)(b * 128 + oc0)     * 128 + y) * 128) + px;
    float* r1 = out + (((size_t)(b * 128 + oc0 + 8) * 128 + y) * 128) + px;
#pragma unroll
    for (int nt = 0; nt < 8; nt++) {
        int p = nt * 8 + 2 * tig;
        r0[2 * p]       = d[nt][0];
        r0[2 * (p + 1)] = d[nt][1];
        r1[2 * p]       = d[nt][2];
        r1[2 * (p + 1)] = d[nt][3];
    }
}

// ---------------- BN2 apply + ReLU ----------------
__global__ void bn_apply_kernel(float* __restrict__ out) {
    int i = blockIdx.x * 256 + threadIdx.x;
    int c = (i >> 12) & 127;
    float sc = g_bn2s[c], sh = g_bn2b[c];
    float4 v = ((float4*)out)[i];
    v.x = fmaxf(v.x * sc + sh, 0.f);
    v.y = fmaxf(v.y * sc + sh, 0.f);
    v.z = fmaxf(v.z * sc + sh, 0.f);
    v.w = fmaxf(v.w * sc + sh, 0.f);
    ((float4*)out)[i] = v;
}

// ---------------- launch ----------------
extern "C" void kernel_launch(void* const* d_in, const int* in_sizes, int n_in,
                              void* d_out, int out_size) {
    const float* x     = (const float*)d_in[0];
    const float* off_w = (const float*)d_in[1];
    const float* off_b = (const float*)d_in[2];
    const float* dcn_w = (const float*)d_in[3];
    const float* dcn_b = (const float*)d_in[4];
    const float* bn1_g = (const float*)d_in[5];
    const float* bn1_b = (const float*)d_in[6];
    const float* up_w  = (const float*)d_in[7];
    const float* bn2_g = (const float*)d_in[8];
    const float* bn2_b = (const float*)d_in[9];
    float* out = (float*)d_out;

    prep_kernel<<<288, 256>>>(dcn_w, up_w);
    nhwc_kernel<<<dim3(128, 8, 4), dim3(32, 8)>>>(x);
    offset_conv_kernel<<<256, 512>>>(x, off_w, off_b);
    deform_kernel<<<512, 256>>>(dcn_b);
    bn_partial_kernel<<<512, 128>>>(nullptr, 0);
    bn_final_kernel<<<1, 128>>>(bn1_g, bn1_b, 0);
    transp_kernel<<<1024, 256>>>(out);
    bn_partial_kernel<<<512, 128>>>(out, 1);
    bn_final_kernel<<<1, 128>>>(bn2_g, bn2_b, 1);
    bn_apply_kernel<<<8192, 256>>>(out);
}

// round 15
// speedup vs baseline: 1.0287x; 1.0032x over previous
#include <cuda_runtime.h>
#include <cuda_bf16.h>
#include <cstdint>
#include <math.h>

#define Bsz  4
#define CIN  256
#define COUT 128
#define HW   4096

// ---------------- device scratch ----------------
__device__ float g_xt[Bsz * HW * CIN];        // NHWC x
__device__ float g_off[Bsz][27][HW];
__device__ float g_out1[Bsz][COUT][HW];
__device__ uint4 g_wAhi[16 * 18 * 8 * 32];    // deform A-fragments (tf32 hi)
__device__ uint4 g_wAlo[16 * 18 * 8 * 32];    // deform A-fragments (tf32 lo)
__device__ uint4 g_wBhi[4 * 8 * 8 * 8 * 32];  // transp A-fragments per parity (tf32 hi)
__device__ uint4 g_wBlo[4 * 8 * 8 * 8 * 32];  // transp A-fragments per parity (tf32 lo)
__device__ float g_bn1s[COUT], g_bn1b[COUT];
__device__ float g_bn2s[COUT], g_bn2b[COUT];
__device__ float g_psum[2][512][2];

__device__ __forceinline__ unsigned f2tf(float f) {
    unsigned u;
    asm("cvt.rna.tf32.f32 %0, %1;" : "=r"(u) : "f"(f));
    return u;
}

// ---------------- weight prep ----------------
__global__ void prep_kernel(const float* __restrict__ dcn_w,
                            const float* __restrict__ up_w) {
    int i = blockIdx.x * blockDim.x + threadIdx.x;
    if (i < 73728) {                       // deform: 16 cb * 18 kc * 8 wr * 32 lanes
        int lane = i & 31;
        int wr   = (i >> 5) & 7;
        int ck   = i >> 8;
        int kc   = ck % 18;
        int cb   = ck / 18;
        int g    = lane >> 2;
        int tig  = lane & 3;
        int row0 = wr * 16 + g,  row1 = row0 + 8;
        int col0 = kc * 8 + tig, col1 = col0 + 4;
        float w0 = dcn_w[row0 * 2304 + (cb * 16 + (col0 & 15)) * 9 + (col0 >> 4)];
        float w1 = dcn_w[row1 * 2304 + (cb * 16 + (col0 & 15)) * 9 + (col0 >> 4)];
        float w2 = dcn_w[row0 * 2304 + (cb * 16 + (col1 & 15)) * 9 + (col1 >> 4)];
        float w3 = dcn_w[row1 * 2304 + (cb * 16 + (col1 & 15)) * 9 + (col1 >> 4)];
        unsigned h0 = f2tf(w0), h1 = f2tf(w1), h2 = f2tf(w2), h3 = f2tf(w3);
        g_wAhi[i] = make_uint4(h0, h1, h2, h3);
        g_wAlo[i] = make_uint4(f2tf(w0 - __uint_as_float(h0)),
                               f2tf(w1 - __uint_as_float(h1)),
                               f2tf(w2 - __uint_as_float(h2)),
                               f2tf(w3 - __uint_as_float(h3)));
    }
    if (i < 65536) {                       // transp: 4 par * 8 cb * 8 kc * 8 wr * 32 lanes
        int lane = i & 31;
        int wr   = (i >> 5) & 7;
        int kc   = (i >> 8) & 7;
        int cb   = (i >> 11) & 7;
        int par  = i >> 14;
        int py = par >> 1, px = par & 1;
        int g = lane >> 2, tig = lane & 3;
        int row0 = wr * 16 + g, row1 = row0 + 8;
        int col0 = kc * 8 + tig, col1 = col0 + 4;
        auto wval = [&](int row, int col) -> float {
            int ci = col >> 2, ts = col & 3;
            int t = ts >> 1, s = ts & 1;
            int ch = cb * 16 + ci;
            int ky = py + 2 * t, kx = px + 2 * s;
            return up_w[((ch * 128 + row) * 4 + (3 - ky)) * 4 + (3 - kx)];
        };
        float w0 = wval(row0, col0), w1 = wval(row1, col0);
        float w2 = wval(row0, col1), w3 = wval(row1, col1);
        unsigned h0 = f2tf(w0), h1 = f2tf(w1), h2 = f2tf(w2), h3 = f2tf(w3);
        g_wBhi[i] = make_uint4(h0, h1, h2, h3);
        g_wBlo[i] = make_uint4(f2tf(w0 - __uint_as_float(h0)),
                               f2tf(w1 - __uint_as_float(h1)),
                               f2tf(w2 - __uint_as_float(h2)),
                               f2tf(w3 - __uint_as_float(h3)));
    }
}

// ---------------- NCHW -> NHWC transpose of x ----------------
__global__ void nhwc_kernel(const float* __restrict__ x) {
    __shared__ float t[32][33];
    int b  = blockIdx.z;
    int p0 = blockIdx.x * 32;
    int c0 = blockIdx.y * 32;
    int tx = threadIdx.x, ty = threadIdx.y;
#pragma unroll
    for (int i = 0; i < 4; i++)
        t[ty + i * 8][tx] = x[((size_t)(b * CIN + c0 + ty + i * 8)) * HW + p0 + tx];
    __syncthreads();
#pragma unroll
    for (int i = 0; i < 4; i++)
        g_xt[((size_t)(b * HW + p0 + ty + i * 8)) * CIN + c0 + tx] = t[tx][ty + i * 8];
}

// ---------------- offset conv: 3x3, 256 -> 27, pad 1 ----------------
#define OG 8
__global__ void offset_conv_kernel(const float* __restrict__ x,
                                   const float* __restrict__ off_w,
                                   const float* __restrict__ off_b) {
    int bh = blockIdx.x;
    int b = bh >> 6, h = bh & 63;
    int g = threadIdx.x >> 6;
    int w = threadIdx.x & 63;
    __shared__ float srow[OG][3][64];
    __shared__ float sws[OG][324];
    __shared__ float red[OG][64];

    float acc[27];
#pragma unroll
    for (int i = 0; i < 27; i++) acc[i] = 0.f;

    const float* xb = x + (size_t)b * CIN * HW;
    for (int cc = 0; cc < CIN / OG; cc++) {
        int c = g * (CIN / OG) + cc;
#pragma unroll
        for (int r = 0; r < 3; r++) {
            int hh = h + r - 1;
            srow[g][r][w] = (hh >= 0 && hh < 64) ? xb[(size_t)c * HW + hh * 64 + w] : 0.f;
        }
        const float* wc = off_w + c * 9;
        for (int j = w; j < 243; j += 64) {
            int oc = j / 9, tap = j - oc * 9;
            sws[g][oc * 12 + tap] = wc[(size_t)oc * (CIN * 9) + tap];
        }
        __syncthreads();
        float xv[9];
#pragma unroll
        for (int tap = 0; tap < 9; tap++) {
            int col = w + (tap % 3) - 1;
            xv[tap] = (col >= 0 && col < 64) ? srow[g][tap / 3][col] : 0.f;
        }
#pragma unroll
        for (int oc = 0; oc < 27; oc++) {
            const float4* wv = (const float4*)&sws[g][oc * 12];
            float4 w0 = wv[0], w1 = wv[1], w2 = wv[2];
            float a = acc[oc];
            a = fmaf(w0.x, xv[0], a); a = fmaf(w0.y, xv[1], a);
            a = fmaf(w0.z, xv[2], a); a = fmaf(w0.w, xv[3], a);
            a = fmaf(w1.x, xv[4], a); a = fmaf(w1.y, xv[5], a);
            a = fmaf(w1.z, xv[6], a); a = fmaf(w1.w, xv[7], a);
            a = fmaf(w2.x, xv[8], a);
            acc[oc] = a;
        }
        __syncthreads();
    }
    for (int oc = 0; oc < 27; oc++) {
        red[g][w] = acc[oc];
        __syncthreads();
        if (g == 0) {
            float v = red[0][w] + red[1][w] + red[2][w] + red[3][w]
                    + red[4][w] + red[5][w] + red[6][w] + red[7][w] + off_b[oc];
            if (oc >= 18) v = 1.f / (1.f + __expf(-v));
            g_off[b][oc][h * 64 + w] = v;
        }
        __syncthreads();
    }
}

// ---------------- deformable conv (db fp32 ssam + cvt in loop; lean smem) ---
#define SSP2 36
__device__ __forceinline__ void dgather(int tid, int cb, float* sbuf,
                                        const float* __restrict__ xtb,
                                        const ushort4* sidx, const float4* swt) {
    for (int it = tid; it < 1152; it += 256) {
        int c = it & 15;
        int kp = it >> 4;
        int k = kp >> 3;
        int p4 = kp & 7;
        const float* xc = xtb + cb * 16 + c;
        float4 v;
        float* vp = &v.x;
#pragma unroll
        for (int j = 0; j < 4; j++) {
            int e = k * 32 + p4 * 4 + j;
            ushort4 id = sidx[e];
            float4 wt = swt[e];
            float r =      wt.x * __ldg(xc + (int)id.x * CIN);
            r = fmaf(wt.y, __ldg(xc + (int)id.y * CIN), r);
            r = fmaf(wt.z, __ldg(xc + (int)id.z * CIN), r);
            r = fmaf(wt.w, __ldg(xc + (int)id.w * CIN), r);
            vp[j] = r;
        }
        *(float4*)&sbuf[(k * 16 + c) * SSP2 + p4 * 4] = v;
    }
}

#define MMA_TF32(d, a, b0, b1) \
    asm volatile("mma.sync.aligned.m16n8k8.row.col.f32.tf32.tf32.f32 " \
        "{%0,%1,%2,%3}, {%4,%5,%6,%7}, {%8,%9}, {%0,%1,%2,%3};" \
        : "+f"((d)[0]), "+f"((d)[1]), "+f"((d)[2]), "+f"((d)[3]) \
        : "r"((a).x), "r"((a).y), "r"((a).z), "r"((a).w), "r"(b0), "r"(b1))

__global__ void __launch_bounds__(256) deform_kernel(const float* __restrict__ dcn_b) {
    int blk = blockIdx.x;
    int b = blk >> 7;
    int t = blk & 127;
    int h = t >> 1;
    int w0 = (t & 1) << 5;
    int p0 = h * 64 + w0;
    int tid = threadIdx.x;
    int lane = tid & 31, wid = tid >> 5;

    __shared__ ushort4 sidx[288];
    __shared__ float4  swt[288];
    __shared__ __align__(16) float ssam[2][144 * SSP2];

    for (int e = tid; e < 288; e += 256) {
        int k = e >> 5, p = e & 31;
        float dy = g_off[b][k][p0 + p];
        float dx = g_off[b][9 + k][p0 + p];
        float m  = g_off[b][18 + k][p0 + p];
        float py = dy + (float)(k / 3 - 1 + h);
        float px = dx + (float)(k % 3 - 1 + w0 + p);
        float y0f = floorf(py), x0f = floorf(px);
        int y0 = (int)y0f, x0i = (int)x0f;
        float wy = py - y0f, wx = px - x0f;
        float w00 = (1.f - wy) * (1.f - wx) * m;
        float w01 = (1.f - wy) * wx * m;
        float w10 = wy * (1.f - wx) * m;
        float w11 = wy * wx * m;
        int y1 = y0 + 1, x1i = x0i + 1;
        bool y0v = (unsigned)y0  < 64u, y1v = (unsigned)y1  < 64u;
        bool x0v = (unsigned)x0i < 64u, x1v = (unsigned)x1i < 64u;
        int y0c = min(max(y0, 0), 63),  y1c = min(max(y1, 0), 63);
        int x0c = min(max(x0i, 0), 63), x1c = min(max(x1i, 0), 63);
        sidx[e] = make_ushort4((unsigned short)(y0c * 64 + x0c),
                               (unsigned short)(y0c * 64 + x1c),
                               (unsigned short)(y1c * 64 + x0c),
                               (unsigned short)(y1c * 64 + x1c));
        swt[e] = make_float4(y0v && x0v ? w00 : 0.f,
                             y0v && x1v ? w01 : 0.f,
                             y1v && x0v ? w10 : 0.f,
                             y1v && x1v ? w11 : 0.f);
    }
    __syncthreads();

    int g   = lane >> 2;
    int tig = lane & 3;

    float d[4][4];
#pragma unroll
    for (int i = 0; i < 4; i++)
#pragma unroll
        for (int j = 0; j < 4; j++) d[i][j] = 0.f;

    unsigned sbase = (unsigned)__cvta_generic_to_shared(&ssam[0][0]);
    const float* xtb = g_xt + (size_t)b * HW * CIN;

    dgather(tid, 0, &ssam[0][0], xtb, sidx, swt);
    __syncthreads();

#pragma unroll 1
    for (int cb = 0; cb < 16; cb++) {
        if (cb < 15) dgather(tid, cb + 1, &ssam[(cb + 1) & 1][0], xtb, sidx, swt);
        const uint4* ph = g_wAhi + ((cb * 18) * 8 + wid) * 32 + lane;
        const uint4* pl = g_wAlo + ((cb * 18) * 8 + wid) * 32 + lane;
        unsigned sb = sbase + (cb & 1) * (144 * SSP2 * 4);
#pragma unroll 2
        for (int kc = 0; kc < 18; kc++) {
            uint4 ah = __ldg(ph + kc * 256);
            uint4 al = __ldg(pl + kc * 256);
            unsigned base0 = sb + ((kc * 8 + tig) * SSP2 + g) * 4;
            unsigned base1 = base0 + 4 * SSP2 * 4;
#pragma unroll
            for (int nt = 0; nt < 4; nt++) {
                float s0, s1;
                asm volatile("ld.shared.f32 %0, [%1];" : "=f"(s0) : "r"(base0 + nt * 32));
                asm volatile("ld.shared.f32 %0, [%1];" : "=f"(s1) : "r"(base1 + nt * 32));
                unsigned bh0 = f2tf(s0), bh1 = f2tf(s1);
                unsigned bl0 = f2tf(s0 - __uint_as_float(bh0));
                unsigned bl1 = f2tf(s1 - __uint_as_float(bh1));
                MMA_TF32(d[nt], ah, bh0, bh1);
                MMA_TF32(d[nt], al, bh0, bh1);
                MMA_TF32(d[nt], ah, bl0, bl1);
            }
        }
        __syncthreads();
    }

    int oc0 = wid * 16 + g;
    float bias0 = dcn_b[oc0], bias1 = dcn_b[oc0 + 8];
    float* r0 = &g_out1[b][oc0][p0];
    float* r1 = &g_out1[b][oc0 + 8][p0];
#pragma unroll
    for (int nt = 0; nt < 4; nt++) {
        int col = nt * 8 + 2 * tig;
        *(float2*)(r0 + col) = make_float2(d[nt][0] + bias0, d[nt][1] + bias0);
        *(float2*)(r1 + col) = make_float2(d[nt][2] + bias1, d[nt][3] + bias1);
    }
}

// ---------------- BN stats ----------------
__global__ void bn_partial_kernel(const float* __restrict__ ext, int which) {
    int bx = blockIdx.x;
    int c = bx >> 2, b = bx & 3;
    const float* plane = which ? ext + (size_t)(b * 128 + c) * 16384
                               : &g_out1[b][c][0];
    int n4 = which ? 4096 : 1024;
    float s = 0.f, s2 = 0.f;
    const float4* p4 = (const float4*)plane;
    for (int i = threadIdx.x; i < n4; i += 128) {
        float4 v = p4[i];
        s  += v.x + v.y + v.z + v.w;
        s2 += v.x*v.x + v.y*v.y + v.z*v.z + v.w*v.w;
    }
    __shared__ float rs[128], rq[128];
    rs[threadIdx.x] = s; rq[threadIdx.x] = s2;
    __syncthreads();
    for (int st = 64; st > 0; st >>= 1) {
        if (threadIdx.x < st) {
            rs[threadIdx.x] += rs[threadIdx.x + st];
            rq[threadIdx.x] += rq[threadIdx.x + st];
        }
        __syncthreads();
    }
    if (threadIdx.x == 0) {
        g_psum[which][bx][0] = rs[0];
        g_psum[which][bx][1] = rq[0];
    }
}

__global__ void bn_final_kernel(const float* __restrict__ gamma,
                                const float* __restrict__ beta, int which) {
    int c = threadIdx.x;
    float s = 0.f, s2 = 0.f;
#pragma unroll
    for (int b = 0; b < 4; b++) {
        s  += g_psum[which][c * 4 + b][0];
        s2 += g_psum[which][c * 4 + b][1];
    }
    float n  = which ? 65536.f : 16384.f;
    float mu = s / n;
    float var = s2 / n - mu * mu;
    float sc = gamma[c] * rsqrtf(var + 1e-5f);
    float sh = beta[c] - mu * sc;
    if (which == 0) { g_bn1s[c] = sc; g_bn1b[c] = sh; }
    else            { g_bn2s[c] = sc; g_bn2b[c] = sh; }
}

// ---------------- transposed conv via 3xTF32 mma.sync (u2 hi/lo ssam) -------
#define SSP 68
__global__ void __launch_bounds__(256) transp_kernel(float* __restrict__ out) {
    int blk = blockIdx.x;
    int u   = blk & 63;
    int par = (blk >> 6) & 3;
    int b   = blk >> 8;
    int py = par >> 1, px = par & 1;
    int tid = threadIdx.x;
    int lane = tid & 31, wid = tid >> 5;

    __shared__ float srow[16 * 2 * 64];
    __shared__ __align__(16) uint2 ssam[64 * SSP];

    int g = lane >> 2, tig = lane & 3;

    float d[8][4];
#pragma unroll
    for (int i = 0; i < 8; i++)
#pragma unroll
        for (int j = 0; j < 4; j++) d[i][j] = 0.f;

    unsigned sbase = (unsigned)__cvta_generic_to_shared(ssam);

#pragma unroll 1
    for (int cb = 0; cb < 8; cb++) {
        for (int e = tid; e < 512; e += 256) {
            int ci = e >> 5;
            int tt = (e >> 4) & 1;
            int f4 = e & 15;
            int c  = cb * 16 + ci;
            int row = u + py - 1 + tt;
            float4 v = make_float4(0.f, 0.f, 0.f, 0.f);
            if ((unsigned)row < 64u) {
                float4 r = *(const float4*)&g_out1[b][c][row * 64 + f4 * 4];
                float sc = g_bn1s[c], sh = g_bn1b[c];
                v.x = fmaxf(fmaf(r.x, sc, sh), 0.f);
                v.y = fmaxf(fmaf(r.y, sc, sh), 0.f);
                v.z = fmaxf(fmaf(r.z, sc, sh), 0.f);
                v.w = fmaxf(fmaf(r.w, sc, sh), 0.f);
            }
            *(float4*)&srow[(ci * 2 + tt) * 64 + f4 * 4] = v;
        }
        __syncthreads();
        for (int e = tid; e < 4096; e += 256) {
            int ck = e >> 6;
            int p  = e & 63;
            int ci = ck >> 2;
            int tt = (ck >> 1) & 1;
            int s  = ck & 1;
            int col = p + px - 1 + s;
            float v = (col >= 0 && col < 64) ? srow[(ci * 2 + tt) * 64 + col] : 0.f;
            unsigned hi = f2tf(v);
            unsigned lo = f2tf(v - __uint_as_float(hi));
            ssam[ck * SSP + p] = make_uint2(hi, lo);
        }
        __syncthreads();
        const uint4* ph = g_wBhi + (((par * 8 + cb) * 8) * 8 + wid) * 32 + lane;
        const uint4* pl = g_wBlo + (((par * 8 + cb) * 8) * 8 + wid) * 32 + lane;
#pragma unroll 2
        for (int kc = 0; kc < 8; kc++) {
            uint4 ah = __ldg(ph + kc * 256);
            uint4 al = __ldg(pl + kc * 256);
            unsigned base0 = sbase + ((kc * 8 + tig) * SSP + g) * 8;
            unsigned base1 = base0 + 4 * SSP * 8;
#pragma unroll
            for (int nt = 0; nt < 8; nt++) {
                unsigned h0, l0, h1, l1;
                asm volatile("ld.shared.v2.u32 {%0,%1}, [%2];"
                             : "=r"(h0), "=r"(l0) : "r"(base0 + nt * 64));
                asm volatile("ld.shared.v2.u32 {%0,%1}, [%2];"
                             : "=r"(h1), "=r"(l1) : "r"(base1 + nt * 64));
                MMA_TF32(d[nt], ah, h0, h1);
                MMA_TF32(d[nt], al, h0, h1);
                MMA_TF32(d[nt], ah, l0, l1);
            }
        }
        __syncthreads();
    }

    int y = 2 * u + py;
    int oc0 = wid * 16 + g;
    float* r0 = out + (((size_t)(b * 128 + oc0)     * 128 + y) * 128) + px;
    float* r1 = out + (((size_t)(b * 128 + oc0 + 8) * 128 + y) * 128) + px;
#pragma unroll
    for (int nt = 0; nt < 8; nt++) {
        int p = nt * 8 + 2 * tig;
        r0[2 * p]       = d[nt][0];
        r0[2 * (p + 1)] = d[nt][1];
        r1[2 * p]       = d[nt][2];
        r1[2 * (p + 1)] = d[nt][3];
    }
}

// ---------------- BN2 apply + ReLU ----------------
__global__ void bn_apply_kernel(float* __restrict__ out) {
    int i = blockIdx.x * 256 + threadIdx.x;
    int c = (i >> 12) & 127;
    float sc = g_bn2s[c], sh = g_bn2b[c];
    float4 v = ((float4*)out)[i];
    v.x = fmaxf(v.x * sc + sh, 0.f);
    v.y = fmaxf(v.y * sc + sh, 0.f);
    v.z = fmaxf(v.z * sc + sh, 0.f);
    v.w = fmaxf(v.w * sc + sh, 0.f);
    ((float4*)out)[i] = v;
}

// ---------------- launch ----------------
extern "C" void kernel_launch(void* const* d_in, const int* in_sizes, int n_in,
                              void* d_out, int out_size) {
    const float* x     = (const float*)d_in[0];
    const float* off_w = (const float*)d_in[1];
    const float* off_b = (const float*)d_in[2];
    const float* dcn_w = (const float*)d_in[3];
    const float* dcn_b = (const float*)d_in[4];
    const float* bn1_g = (const float*)d_in[5];
    const float* bn1_b = (const float*)d_in[6];
    const float* up_w  = (const float*)d_in[7];
    const float* bn2_g = (const float*)d_in[8];
    const float* bn2_b = (const float*)d_in[9];
    float* out = (float*)d_out;

    // Ask for maximum shared-memory carveout so deform can fit 4 CTAs/SM.
    cudaFuncSetAttribute(deform_kernel,
                         cudaFuncAttributePreferredSharedMemoryCarveout, 100);
    cudaFuncSetAttribute(transp_kernel,
                         cudaFuncAttributePreferredSharedMemoryCarveout, 100);

    prep_kernel<<<288, 256>>>(dcn_w, up_w);
    nhwc_kernel<<<dim3(128, 8, 4), dim3(32, 8)>>>(x);
    offset_conv_kernel<<<256, 512>>>(x, off_w, off_b);
    deform_kernel<<<512, 256>>>(dcn_b);
    bn_partial_kernel<<<512, 128>>>(nullptr, 0);
    bn_final_kernel<<<1, 128>>>(bn1_g, bn1_b, 0);
    transp_kernel<<<1024, 256>>>(out);
    bn_partial_kernel<<<512, 128>>>(out, 1);
    bn_final_kernel<<<1, 128>>>(bn2_g, bn2_b, 1);
    bn_apply_kernel<<<8192, 256>>>(out);
}

// round 16
// speedup vs baseline: 1.1123x; 1.0812x over previous
#include <cuda_runtime.h>
#include <cuda_bf16.h>
#include <cstdint>
#include <math.h>

#define Bsz  4
#define CIN  256
#define COUT 128
#define HW   4096

// ---------------- device scratch ----------------
__device__ float g_xt[Bsz * HW * CIN];        // NHWC x
__device__ float g_off[Bsz][27][HW];
__device__ float g_out1[Bsz][COUT][HW];
__device__ uint4 g_wAhi[16 * 18 * 8 * 32];    // deform A-fragments (tf32 hi)
__device__ uint4 g_wAlo[16 * 18 * 8 * 32];    // deform A-fragments (tf32 lo)
__device__ uint4 g_wBhi[4 * 8 * 8 * 8 * 32];  // transp A-fragments per parity (tf32 hi)
__device__ uint4 g_wBlo[4 * 8 * 8 * 8 * 32];  // transp A-fragments per parity (tf32 lo)
__device__ uint4 g_wOhi[16 * 18 * 2 * 32];    // offset A-fragments (tf32 hi), M=32 pad
__device__ uint4 g_wOlo[16 * 18 * 2 * 32];    // offset A-fragments (tf32 lo)
__device__ float g_bn1s[COUT], g_bn1b[COUT];
__device__ float g_bn2s[COUT], g_bn2b[COUT];
__device__ float g_psum[2][512][2];

__device__ __forceinline__ unsigned f2tf(float f) {
    unsigned u;
    asm("cvt.rna.tf32.f32 %0, %1;" : "=r"(u) : "f"(f));
    return u;
}

// ---------------- weight prep ----------------
__global__ void prep_kernel(const float* __restrict__ dcn_w,
                            const float* __restrict__ up_w,
                            const float* __restrict__ off_w) {
    int i = blockIdx.x * blockDim.x + threadIdx.x;
    if (i < 73728) {                       // deform: 16 cb * 18 kc * 8 wr * 32 lanes
        int lane = i & 31;
        int wr   = (i >> 5) & 7;
        int ck   = i >> 8;
        int kc   = ck % 18;
        int cb   = ck / 18;
        int g    = lane >> 2;
        int tig  = lane & 3;
        int row0 = wr * 16 + g,  row1 = row0 + 8;
        int col0 = kc * 8 + tig, col1 = col0 + 4;
        float w0 = dcn_w[row0 * 2304 + (cb * 16 + (col0 & 15)) * 9 + (col0 >> 4)];
        float w1 = dcn_w[row1 * 2304 + (cb * 16 + (col0 & 15)) * 9 + (col0 >> 4)];
        float w2 = dcn_w[row0 * 2304 + (cb * 16 + (col1 & 15)) * 9 + (col1 >> 4)];
        float w3 = dcn_w[row1 * 2304 + (cb * 16 + (col1 & 15)) * 9 + (col1 >> 4)];
        unsigned h0 = f2tf(w0), h1 = f2tf(w1), h2 = f2tf(w2), h3 = f2tf(w3);
        g_wAhi[i] = make_uint4(h0, h1, h2, h3);
        g_wAlo[i] = make_uint4(f2tf(w0 - __uint_as_float(h0)),
                               f2tf(w1 - __uint_as_float(h1)),
                               f2tf(w2 - __uint_as_float(h2)),
                               f2tf(w3 - __uint_as_float(h3)));
    }
    if (i < 65536) {                       // transp: 4 par * 8 cb * 8 kc * 8 wr * 32 lanes
        int lane = i & 31;
        int wr   = (i >> 5) & 7;
        int kc   = (i >> 8) & 7;
        int cb   = (i >> 11) & 7;
        int par  = i >> 14;
        int py = par >> 1, px = par & 1;
        int g = lane >> 2, tig = lane & 3;
        int row0 = wr * 16 + g, row1 = row0 + 8;
        int col0 = kc * 8 + tig, col1 = col0 + 4;
        auto wval = [&](int row, int col) -> float {
            int ci = col >> 2, ts = col & 3;
            int t = ts >> 1, s = ts & 1;
            int ch = cb * 16 + ci;
            int ky = py + 2 * t, kx = px + 2 * s;
            return up_w[((ch * 128 + row) * 4 + (3 - ky)) * 4 + (3 - kx)];
        };
        float w0 = wval(row0, col0), w1 = wval(row1, col0);
        float w2 = wval(row0, col1), w3 = wval(row1, col1);
        unsigned h0 = f2tf(w0), h1 = f2tf(w1), h2 = f2tf(w2), h3 = f2tf(w3);
        g_wBhi[i] = make_uint4(h0, h1, h2, h3);
        g_wBlo[i] = make_uint4(f2tf(w0 - __uint_as_float(h0)),
                               f2tf(w1 - __uint_as_float(h1)),
                               f2tf(w2 - __uint_as_float(h2)),
                               f2tf(w3 - __uint_as_float(h3)));
    }
    if (i < 18432) {                       // offset: 16 cb * 18 kc * 2 wr * 32 lanes
        int lane = i & 31;
        int wr   = (i >> 5) & 1;
        int kc   = (i >> 6) % 18;
        int cb   = i / 1152;
        int g = lane >> 2, tig = lane & 3;
        int row0 = wr * 16 + g, row1 = row0 + 8;
        int col0 = kc * 8 + tig, col1 = col0 + 4;
        auto wval = [&](int m, int col) -> float {
            if (m >= 27) return 0.f;
            int c = col / 9, tap = col - c * 9;
            return off_w[((size_t)m * 256 + cb * 16 + c) * 9 + tap];
        };
        float w0 = wval(row0, col0), w1 = wval(row1, col0);
        float w2 = wval(row0, col1), w3 = wval(row1, col1);
        unsigned h0 = f2tf(w0), h1 = f2tf(w1), h2 = f2tf(w2), h3 = f2tf(w3);
        g_wOhi[i] = make_uint4(h0, h1, h2, h3);
        g_wOlo[i] = make_uint4(f2tf(w0 - __uint_as_float(h0)),
                               f2tf(w1 - __uint_as_float(h1)),
                               f2tf(w2 - __uint_as_float(h2)),
                               f2tf(w3 - __uint_as_float(h3)));
    }
}

// ---------------- NCHW -> NHWC transpose of x ----------------
__global__ void nhwc_kernel(const float* __restrict__ x) {
    __shared__ float t[32][33];
    int b  = blockIdx.z;
    int p0 = blockIdx.x * 32;
    int c0 = blockIdx.y * 32;
    int tx = threadIdx.x, ty = threadIdx.y;
#pragma unroll
    for (int i = 0; i < 4; i++)
        t[ty + i * 8][tx] = x[((size_t)(b * CIN + c0 + ty + i * 8)) * HW + p0 + tx];
    __syncthreads();
#pragma unroll
    for (int i = 0; i < 4; i++)
        g_xt[((size_t)(b * HW + p0 + ty + i * 8)) * CIN + c0 + tx] = t[tx][ty + i * 8];
}

#define MMA_TF32(d, a, b0, b1) \
    asm volatile("mma.sync.aligned.m16n8k8.row.col.f32.tf32.tf32.f32 " \
        "{%0,%1,%2,%3}, {%4,%5,%6,%7}, {%8,%9}, {%0,%1,%2,%3};" \
        : "+f"((d)[0]), "+f"((d)[1]), "+f"((d)[2]), "+f"((d)[3]) \
        : "r"((a).x), "r"((a).y), "r"((a).z), "r"((a).w), "r"(b0), "r"(b1))

// ---------------- offset conv via 3xTF32 mma.sync ----------------
// grid = B*64 (block = (b, row) = 64 px), block = 256 (8 warps = 2 m x 4 px-quarters)
#define OSSP 68
#define OFF_SROW_F (16 * 3 * 64)
#define OFF_SMEM ((OFF_SROW_F + 144 * OSSP) * 4)
__global__ void __launch_bounds__(256) offset_conv_kernel(const float* __restrict__ x,
                                                          const float* __restrict__ off_b) {
    extern __shared__ __align__(16) float osm[];
    float* srow = osm;                    // [c][r][px]
    float* ssam = osm + OFF_SROW_F;       // [ck=c*9+tap][px]

    int bh = blockIdx.x;
    int b = bh >> 6, h = bh & 63;
    int tid = threadIdx.x;
    int lane = tid & 31, wid = tid >> 5;
    int wr = wid >> 2;                    // m-tile 0..1
    int ng = wid & 3;                     // px quarter
    int g = lane >> 2, tig = lane & 3;

    float d[2][4];
#pragma unroll
    for (int i = 0; i < 2; i++)
#pragma unroll
        for (int j = 0; j < 4; j++) d[i][j] = 0.f;

    unsigned sbase = (unsigned)__cvta_generic_to_shared(ssam);

#pragma unroll 1
    for (int cb = 0; cb < 16; cb++) {
        // stage 3 rows x 16 channels (float4)
        for (int e = tid; e < 768; e += 256) {
            int c  = e / 48;
            int rr = (e / 16) % 3;
            int f4 = e % 16;
            int row = h + rr - 1;
            float4 v = make_float4(0.f, 0.f, 0.f, 0.f);
            if ((unsigned)row < 64u)
                v = *(const float4*)(x + ((size_t)(b * CIN + cb * 16 + c)) * HW + row * 64 + f4 * 4);
            *(float4*)&srow[(c * 3 + rr) * 64 + f4 * 4] = v;
        }
        __syncthreads();
        // expand: ssam[c*9+tap][p] = srow[c][tap/3][p + tap%3 - 1] (0 OOB)
        for (int e = tid; e < 9216; e += 256) {
            int ck = e >> 6, p = e & 63;
            int c = ck / 9, tap = ck - c * 9;
            int col = p + (tap % 3) - 1;
            float v = ((unsigned)col < 64u) ? srow[(c * 3 + tap / 3) * 64 + col] : 0.f;
            ssam[ck * OSSP + p] = v;
        }
        __syncthreads();
        const uint4* ph = g_wOhi + (cb * 18 * 2 + wr) * 32 + lane;
        const uint4* pl = g_wOlo + (cb * 18 * 2 + wr) * 32 + lane;
#pragma unroll 2
        for (int kc = 0; kc < 18; kc++) {
            uint4 ah = __ldg(ph + kc * 64);
            uint4 al = __ldg(pl + kc * 64);
            unsigned base0 = sbase + ((kc * 8 + tig) * OSSP + ng * 16 + g) * 4;
            unsigned base1 = base0 + 4 * OSSP * 4;
#pragma unroll
            for (int nt = 0; nt < 2; nt++) {
                float s0, s1;
                asm volatile("ld.shared.f32 %0, [%1];" : "=f"(s0) : "r"(base0 + nt * 32));
                asm volatile("ld.shared.f32 %0, [%1];" : "=f"(s1) : "r"(base1 + nt * 32));
                unsigned bh0 = f2tf(s0), bh1 = f2tf(s1);
                unsigned bl0 = f2tf(s0 - __uint_as_float(bh0));
                unsigned bl1 = f2tf(s1 - __uint_as_float(bh1));
                MMA_TF32(d[nt], ah, bh0, bh1);
                MMA_TF32(d[nt], al, bh0, bh1);
                MMA_TF32(d[nt], ah, bl0, bl1);
            }
        }
        __syncthreads();
    }

    int m0 = wr * 16 + g;
    int m1 = m0 + 8;
    float b0v = (m0 < 27) ? off_b[m0] : 0.f;
    float b1v = (m1 < 27) ? off_b[m1] : 0.f;
#pragma unroll
    for (int nt = 0; nt < 2; nt++) {
        int p = ng * 16 + nt * 8 + 2 * tig;
        float v0 = d[nt][0] + b0v, v1 = d[nt][1] + b0v;
        float v2 = d[nt][2] + b1v, v3 = d[nt][3] + b1v;
        if (m0 >= 18) { v0 = 1.f / (1.f + __expf(-v0)); v1 = 1.f / (1.f + __expf(-v1)); }
        if (m1 >= 18) { v2 = 1.f / (1.f + __expf(-v2)); v3 = 1.f / (1.f + __expf(-v3)); }
        if (m0 < 27) { g_off[b][m0][h * 64 + p] = v0; g_off[b][m0][h * 64 + p + 1] = v1; }
        if (m1 < 27) { g_off[b][m1][h * 64 + p] = v2; g_off[b][m1][h * 64 + p + 1] = v3; }
    }
}

// ---------------- deformable conv (db fp32 ssam + cvt in loop; lean smem) ---
#define SSP2 36
__device__ __forceinline__ void dgather(int tid, int cb, float* sbuf,
                                        const float* __restrict__ xtb,
                                        const ushort4* sidx, const float4* swt) {
    for (int it = tid; it < 1152; it += 256) {
        int c = it & 15;
        int kp = it >> 4;
        int k = kp >> 3;
        int p4 = kp & 7;
        const float* xc = xtb + cb * 16 + c;
        float4 v;
        float* vp = &v.x;
#pragma unroll
        for (int j = 0; j < 4; j++) {
            int e = k * 32 + p4 * 4 + j;
            ushort4 id = sidx[e];
            float4 wt = swt[e];
            float r =      wt.x * __ldg(xc + (int)id.x * CIN);
            r = fmaf(wt.y, __ldg(xc + (int)id.y * CIN), r);
            r = fmaf(wt.z, __ldg(xc + (int)id.z * CIN), r);
            r = fmaf(wt.w, __ldg(xc + (int)id.w * CIN), r);
            vp[j] = r;
        }
        *(float4*)&sbuf[(k * 16 + c) * SSP2 + p4 * 4] = v;
    }
}

__global__ void __launch_bounds__(256) deform_kernel(const float* __restrict__ dcn_b) {
    int blk = blockIdx.x;
    int b = blk >> 7;
    int t = blk & 127;
    int h = t >> 1;
    int w0 = (t & 1) << 5;
    int p0 = h * 64 + w0;
    int tid = threadIdx.x;
    int lane = tid & 31, wid = tid >> 5;

    __shared__ ushort4 sidx[288];
    __shared__ float4  swt[288];
    __shared__ __align__(16) float ssam[2][144 * SSP2];

    for (int e = tid; e < 288; e += 256) {
        int k = e >> 5, p = e & 31;
        float dy = g_off[b][k][p0 + p];
        float dx = g_off[b][9 + k][p0 + p];
        float m  = g_off[b][18 + k][p0 + p];
        float py = dy + (float)(k / 3 - 1 + h);
        float px = dx + (float)(k % 3 - 1 + w0 + p);
        float y0f = floorf(py), x0f = floorf(px);
        int y0 = (int)y0f, x0i = (int)x0f;
        float wy = py - y0f, wx = px - x0f;
        float w00 = (1.f - wy) * (1.f - wx) * m;
        float w01 = (1.f - wy) * wx * m;
        float w10 = wy * (1.f - wx) * m;
        float w11 = wy * wx * m;
        int y1 = y0 + 1, x1i = x0i + 1;
        bool y0v = (unsigned)y0  < 64u, y1v = (unsigned)y1  < 64u;
        bool x0v = (unsigned)x0i < 64u, x1v = (unsigned)x1i < 64u;
        int y0c = min(max(y0, 0), 63),  y1c = min(max(y1, 0), 63);
        int x0c = min(max(x0i, 0), 63), x1c = min(max(x1i, 0), 63);
        sidx[e] = make_ushort4((unsigned short)(y0c * 64 + x0c),
                               (unsigned short)(y0c * 64 + x1c),
                               (unsigned short)(y1c * 64 + x0c),
                               (unsigned short)(y1c * 64 + x1c));
        swt[e] = make_float4(y0v && x0v ? w00 : 0.f,
                             y0v && x1v ? w01 : 0.f,
                             y1v && x0v ? w10 : 0.f,
                             y1v && x1v ? w11 : 0.f);
    }
    __syncthreads();

    int g   = lane >> 2;
    int tig = lane & 3;

    float d[4][4];
#pragma unroll
    for (int i = 0; i < 4; i++)
#pragma unroll
        for (int j = 0; j < 4; j++) d[i][j] = 0.f;

    unsigned sbase = (unsigned)__cvta_generic_to_shared(&ssam[0][0]);
    const float* xtb = g_xt + (size_t)b * HW * CIN;

    dgather(tid, 0, &ssam[0][0], xtb, sidx, swt);
    __syncthreads();

#pragma unroll 1
    for (int cb = 0; cb < 16; cb++) {
        if (cb < 15) dgather(tid, cb + 1, &ssam[(cb + 1) & 1][0], xtb, sidx, swt);
        const uint4* ph = g_wAhi + ((cb * 18) * 8 + wid) * 32 + lane;
        const uint4* pl = g_wAlo + ((cb * 18) * 8 + wid) * 32 + lane;
        unsigned sb = sbase + (cb & 1) * (144 * SSP2 * 4);
#pragma unroll 2
        for (int kc = 0; kc < 18; kc++) {
            uint4 ah = __ldg(ph + kc * 256);
            uint4 al = __ldg(pl + kc * 256);
            unsigned base0 = sb + ((kc * 8 + tig) * SSP2 + g) * 4;
            unsigned base1 = base0 + 4 * SSP2 * 4;
#pragma unroll
            for (int nt = 0; nt < 4; nt++) {
                float s0, s1;
                asm volatile("ld.shared.f32 %0, [%1];" : "=f"(s0) : "r"(base0 + nt * 32));
                asm volatile("ld.shared.f32 %0, [%1];" : "=f"(s1) : "r"(base1 + nt * 32));
                unsigned bh0 = f2tf(s0), bh1 = f2tf(s1);
                unsigned bl0 = f2tf(s0 - __uint_as_float(bh0));
                unsigned bl1 = f2tf(s1 - __uint_as_float(bh1));
                MMA_TF32(d[nt], ah, bh0, bh1);
                MMA_TF32(d[nt], al, bh0, bh1);
                MMA_TF32(d[nt], ah, bl0, bl1);
            }
        }
        __syncthreads();
    }

    int oc0 = wid * 16 + g;
    float bias0 = dcn_b[oc0], bias1 = dcn_b[oc0 + 8];
    float* r0 = &g_out1[b][oc0][p0];
    float* r1 = &g_out1[b][oc0 + 8][p0];
#pragma unroll
    for (int nt = 0; nt < 4; nt++) {
        int col = nt * 8 + 2 * tig;
        *(float2*)(r0 + col) = make_float2(d[nt][0] + bias0, d[nt][1] + bias0);
        *(float2*)(r1 + col) = make_float2(d[nt][2] + bias1, d[nt][3] + bias1);
    }
}

// ---------------- BN stats ----------------
__global__ void bn_partial_kernel(const float* __restrict__ ext, int which) {
    int bx = blockIdx.x;
    int c = bx >> 2, b = bx & 3;
    const float* plane = which ? ext + (size_t)(b * 128 + c) * 16384
                               : &g_out1[b][c][0];
    int n4 = which ? 4096 : 1024;
    float s = 0.f, s2 = 0.f;
    const float4* p4 = (const float4*)plane;
    for (int i = threadIdx.x; i < n4; i += 128) {
        float4 v = p4[i];
        s  += v.x + v.y + v.z + v.w;
        s2 += v.x*v.x + v.y*v.y + v.z*v.z + v.w*v.w;
    }
    __shared__ float rs[128], rq[128];
    rs[threadIdx.x] = s; rq[threadIdx.x] = s2;
    __syncthreads();
    for (int st = 64; st > 0; st >>= 1) {
        if (threadIdx.x < st) {
            rs[threadIdx.x] += rs[threadIdx.x + st];
            rq[threadIdx.x] += rq[threadIdx.x + st];
        }
        __syncthreads();
    }
    if (threadIdx.x == 0) {
        g_psum[which][bx][0] = rs[0];
        g_psum[which][bx][1] = rq[0];
    }
}

__global__ void bn_final_kernel(const float* __restrict__ gamma,
                                const float* __restrict__ beta, int which) {
    int c = threadIdx.x;
    float s = 0.f, s2 = 0.f;
#pragma unroll
    for (int b = 0; b < 4; b++) {
        s  += g_psum[which][c * 4 + b][0];
        s2 += g_psum[which][c * 4 + b][1];
    }
    float n  = which ? 65536.f : 16384.f;
    float mu = s / n;
    float var = s2 / n - mu * mu;
    float sc = gamma[c] * rsqrtf(var + 1e-5f);
    float sh = beta[c] - mu * sc;
    if (which == 0) { g_bn1s[c] = sc; g_bn1b[c] = sh; }
    else            { g_bn2s[c] = sc; g_bn2b[c] = sh; }
}

// ---------------- transposed conv via 3xTF32 mma.sync (u2 hi/lo ssam) -------
#define SSP 68
__global__ void __launch_bounds__(256) transp_kernel(float* __restrict__ out) {
    int blk = blockIdx.x;
    int u   = blk & 63;
    int par = (blk >> 6) & 3;
    int b   = blk >> 8;
    int py = par >> 1, px = par & 1;
    int tid = threadIdx.x;
    int lane = tid & 31, wid = tid >> 5;

    __shared__ float srow[16 * 2 * 64];
    __shared__ __align__(16) uint2 ssam[64 * SSP];

    int g = lane >> 2, tig = lane & 3;

    float d[8][4];
#pragma unroll
    for (int i = 0; i < 8; i++)
#pragma unroll
        for (int j = 0; j < 4; j++) d[i][j] = 0.f;

    unsigned sbase = (unsigned)__cvta_generic_to_shared(ssam);

#pragma unroll 1
    for (int cb = 0; cb < 8; cb++) {
        for (int e = tid; e < 512; e += 256) {
            int ci = e >> 5;
            int tt = (e >> 4) & 1;
            int f4 = e & 15;
            int c  = cb * 16 + ci;
            int row = u + py - 1 + tt;
            float4 v = make_float4(0.f, 0.f, 0.f, 0.f);
            if ((unsigned)row < 64u) {
                float4 r = *(const float4*)&g_out1[b][c][row * 64 + f4 * 4];
                float sc = g_bn1s[c], sh = g_bn1b[c];
                v.x = fmaxf(fmaf(r.x, sc, sh), 0.f);
                v.y = fmaxf(fmaf(r.y, sc, sh), 0.f);
                v.z = fmaxf(fmaf(r.z, sc, sh), 0.f);
                v.w = fmaxf(fmaf(r.w, sc, sh), 0.f);
            }
            *(float4*)&srow[(ci * 2 + tt) * 64 + f4 * 4] = v;
        }
        __syncthreads();
        for (int e = tid; e < 4096; e += 256) {
            int ck = e >> 6;
            int p  = e & 63;
            int ci = ck >> 2;
            int tt = (ck >> 1) & 1;
            int s  = ck & 1;
            int col = p + px - 1 + s;
            float v = (col >= 0 && col < 64) ? srow[(ci * 2 + tt) * 64 + col] : 0.f;
            unsigned hi = f2tf(v);
            unsigned lo = f2tf(v - __uint_as_float(hi));
            ssam[ck * SSP + p] = make_uint2(hi, lo);
        }
        __syncthreads();
        const uint4* ph = g_wBhi + (((par * 8 + cb) * 8) * 8 + wid) * 32 + lane;
        const uint4* pl = g_wBlo + (((par * 8 + cb) * 8) * 8 + wid) * 32 + lane;
#pragma unroll 2
        for (int kc = 0; kc < 8; kc++) {
            uint4 ah = __ldg(ph + kc * 256);
            uint4 al = __ldg(pl + kc * 256);
            unsigned base0 = sbase + ((kc * 8 + tig) * SSP + g) * 8;
            unsigned base1 = base0 + 4 * SSP * 8;
#pragma unroll
            for (int nt = 0; nt < 8; nt++) {
                unsigned h0, l0, h1, l1;
                asm volatile("ld.shared.v2.u32 {%0,%1}, [%2];"
                             : "=r"(h0), "=r"(l0) : "r"(base0 + nt * 64));
                asm volatile("ld.shared.v2.u32 {%0,%1}, [%2];"
                             : "=r"(h1), "=r"(l1) : "r"(base1 + nt * 64));
                MMA_TF32(d[nt], ah, h0, h1);
                MMA_TF32(d[nt], al, h0, h1);
                MMA_TF32(d[nt], ah, l0, l1);
            }
        }
        __syncthreads();
    }

    int y = 2 * u + py;
    int oc0 = wid * 16 + g;
    float* r0 = out + (((size_t)(b * 128 + oc0)     * 128 + y) * 128) + px;
    float* r1 = out + (((size_t)(b * 128 + oc0 + 8) * 128 + y) * 128) + px;
#pragma unroll
    for (int nt = 0; nt < 8; nt++) {
        int p = nt * 8 + 2 * tig;
        r0[2 * p]       = d[nt][0];
        r0[2 * (p + 1)] = d[nt][1];
        r1[2 * p]       = d[nt][2];
        r1[2 * (p + 1)] = d[nt][3];
    }
}

// ---------------- BN2 apply + ReLU ----------------
__global__ void bn_apply_kernel(float* __restrict__ out) {
    int i = blockIdx.x * 256 + threadIdx.x;
    int c = (i >> 12) & 127;
    float sc = g_bn2s[c], sh = g_bn2b[c];
    float4 v = ((float4*)out)[i];
    v.x = fmaxf(v.x * sc + sh, 0.f);
    v.y = fmaxf(v.y * sc + sh, 0.f);
    v.z = fmaxf(v.z * sc + sh, 0.f);
    v.w = fmaxf(v.w * sc + sh, 0.f);
    ((float4*)out)[i] = v;
}

// ---------------- launch ----------------
extern "C" void kernel_launch(void* const* d_in, const int* in_sizes, int n_in,
                              void* d_out, int out_size) {
    const float* x     = (const float*)d_in[0];
    const float* off_w = (const float*)d_in[1];
    const float* off_b = (const float*)d_in[2];
    const float* dcn_w = (const float*)d_in[3];
    const float* dcn_b = (const float*)d_in[4];
    const float* bn1_g = (const float*)d_in[5];
    const float* bn1_b = (const float*)d_in[6];
    const float* up_w  = (const float*)d_in[7];
    const float* bn2_g = (const float*)d_in[8];
    const float* bn2_b = (const float*)d_in[9];
    float* out = (float*)d_out;

    cudaFuncSetAttribute(deform_kernel,
                         cudaFuncAttributePreferredSharedMemoryCarveout, 100);
    cudaFuncSetAttribute(transp_kernel,
                         cudaFuncAttributePreferredSharedMemoryCarveout, 100);
    cudaFuncSetAttribute(offset_conv_kernel,
                         cudaFuncAttributeMaxDynamicSharedMemorySize, OFF_SMEM);
    cudaFuncSetAttribute(offset_conv_kernel,
                         cudaFuncAttributePreferredSharedMemoryCarveout, 100);

    prep_kernel<<<288, 256>>>(dcn_w, up_w, off_w);
    nhwc_kernel<<<dim3(128, 8, 4), dim3(32, 8)>>>(x);
    offset_conv_kernel<<<256, 256, OFF_SMEM>>>(x, off_b);
    deform_kernel<<<512, 256>>>(dcn_b);
    bn_partial_kernel<<<512, 128>>>(nullptr, 0);
    bn_final_kernel<<<1, 128>>>(bn1_g, bn1_b, 0);
    transp_kernel<<<1024, 256>>>(out);
    bn_partial_kernel<<<512, 128>>>(out, 1);
    bn_final_kernel<<<1, 128>>>(bn2_g, bn2_b, 1);
    bn_apply_kernel<<<8192, 256>>>(out);
}

// round 17
// speedup vs baseline: 1.1441x; 1.0287x over previous
#include <cuda_runtime.h>
#include <cuda_bf16.h>
#include <cstdint>
#include <math.h>

#define Bsz  4
#define CIN  256
#define COUT 128
#define HW   4096

// ---------------- device scratch ----------------
__device__ float g_xt[Bsz * HW * CIN];        // NHWC x
__device__ float g_off[Bsz][27][HW];
__device__ float g_out1[Bsz][COUT][HW];
__device__ uint4 g_wAhi[16 * 18 * 8 * 32];    // deform A-fragments (tf32 hi)
__device__ uint4 g_wAlo[16 * 18 * 8 * 32];    // deform A-fragments (tf32 lo)
__device__ uint4 g_wBhi[4 * 8 * 8 * 8 * 32];  // transp A-fragments per parity (tf32 hi)
__device__ uint4 g_wBlo[4 * 8 * 8 * 8 * 32];  // transp A-fragments per parity (tf32 lo)
__device__ uint4 g_wOhi[16 * 18 * 2 * 32];    // offset A-fragments (tf32 hi), M=32 pad
__device__ uint4 g_wOlo[16 * 18 * 2 * 32];    // offset A-fragments (tf32 lo)
__device__ float g_bn1s[COUT], g_bn1b[COUT];
__device__ float g_bn2s[COUT], g_bn2b[COUT];
__device__ float g_psum[2][512][2];

__device__ __forceinline__ unsigned f2tf(float f) {
    unsigned u;
    asm("cvt.rna.tf32.f32 %0, %1;" : "=r"(u) : "f"(f));
    return u;
}

// ---------------- weight prep ----------------
__global__ void prep_kernel(const float* __restrict__ dcn_w,
                            const float* __restrict__ up_w,
                            const float* __restrict__ off_w) {
    int i = blockIdx.x * blockDim.x + threadIdx.x;
    if (i < 73728) {                       // deform: 16 cb * 18 kc * 8 wr * 32 lanes
        int lane = i & 31;
        int wr   = (i >> 5) & 7;
        int ck   = i >> 8;
        int kc   = ck % 18;
        int cb   = ck / 18;
        int g    = lane >> 2;
        int tig  = lane & 3;
        int row0 = wr * 16 + g,  row1 = row0 + 8;
        int col0 = kc * 8 + tig, col1 = col0 + 4;
        float w0 = dcn_w[row0 * 2304 + (cb * 16 + (col0 & 15)) * 9 + (col0 >> 4)];
        float w1 = dcn_w[row1 * 2304 + (cb * 16 + (col0 & 15)) * 9 + (col0 >> 4)];
        float w2 = dcn_w[row0 * 2304 + (cb * 16 + (col1 & 15)) * 9 + (col1 >> 4)];
        float w3 = dcn_w[row1 * 2304 + (cb * 16 + (col1 & 15)) * 9 + (col1 >> 4)];
        unsigned h0 = f2tf(w0), h1 = f2tf(w1), h2 = f2tf(w2), h3 = f2tf(w3);
        g_wAhi[i] = make_uint4(h0, h1, h2, h3);
        g_wAlo[i] = make_uint4(f2tf(w0 - __uint_as_float(h0)),
                               f2tf(w1 - __uint_as_float(h1)),
                               f2tf(w2 - __uint_as_float(h2)),
                               f2tf(w3 - __uint_as_float(h3)));
    }
    if (i < 65536) {                       // transp: 4 par * 8 cb * 8 kc * 8 wr * 32 lanes
        int lane = i & 31;
        int wr   = (i >> 5) & 7;
        int kc   = (i >> 8) & 7;
        int cb   = (i >> 11) & 7;
        int par  = i >> 14;
        int py = par >> 1, px = par & 1;
        int g = lane >> 2, tig = lane & 3;
        int row0 = wr * 16 + g, row1 = row0 + 8;
        int col0 = kc * 8 + tig, col1 = col0 + 4;
        auto wval = [&](int row, int col) -> float {
            int ci = col >> 2, ts = col & 3;
            int t = ts >> 1, s = ts & 1;
            int ch = cb * 16 + ci;
            int ky = py + 2 * t, kx = px + 2 * s;
            return up_w[((ch * 128 + row) * 4 + (3 - ky)) * 4 + (3 - kx)];
        };
        float w0 = wval(row0, col0), w1 = wval(row1, col0);
        float w2 = wval(row0, col1), w3 = wval(row1, col1);
        unsigned h0 = f2tf(w0), h1 = f2tf(w1), h2 = f2tf(w2), h3 = f2tf(w3);
        g_wBhi[i] = make_uint4(h0, h1, h2, h3);
        g_wBlo[i] = make_uint4(f2tf(w0 - __uint_as_float(h0)),
                               f2tf(w1 - __uint_as_float(h1)),
                               f2tf(w2 - __uint_as_float(h2)),
                               f2tf(w3 - __uint_as_float(h3)));
    }
    if (i < 18432) {                       // offset: 16 cb * 18 kc * 2 wr * 32 lanes
        int lane = i & 31;
        int wr   = (i >> 5) & 1;
        int kc   = (i >> 6) % 18;
        int cb   = i / 1152;
        int g = lane >> 2, tig = lane & 3;
        int row0 = wr * 16 + g, row1 = row0 + 8;
        int col0 = kc * 8 + tig, col1 = col0 + 4;
        auto wval = [&](int m, int col) -> float {
            if (m >= 27) return 0.f;
            int c = col / 9, tap = col - c * 9;
            return off_w[((size_t)m * 256 + cb * 16 + c) * 9 + tap];
        };
        float w0 = wval(row0, col0), w1 = wval(row1, col0);
        float w2 = wval(row0, col1), w3 = wval(row1, col1);
        unsigned h0 = f2tf(w0), h1 = f2tf(w1), h2 = f2tf(w2), h3 = f2tf(w3);
        g_wOhi[i] = make_uint4(h0, h1, h2, h3);
        g_wOlo[i] = make_uint4(f2tf(w0 - __uint_as_float(h0)),
                               f2tf(w1 - __uint_as_float(h1)),
                               f2tf(w2 - __uint_as_float(h2)),
                               f2tf(w3 - __uint_as_float(h3)));
    }
}

// ---------------- NCHW -> NHWC transpose of x ----------------
__global__ void nhwc_kernel(const float* __restrict__ x) {
    __shared__ float t[32][33];
    int b  = blockIdx.z;
    int p0 = blockIdx.x * 32;
    int c0 = blockIdx.y * 32;
    int tx = threadIdx.x, ty = threadIdx.y;
#pragma unroll
    for (int i = 0; i < 4; i++)
        t[ty + i * 8][tx] = x[((size_t)(b * CIN + c0 + ty + i * 8)) * HW + p0 + tx];
    __syncthreads();
#pragma unroll
    for (int i = 0; i < 4; i++)
        g_xt[((size_t)(b * HW + p0 + ty + i * 8)) * CIN + c0 + tx] = t[tx][ty + i * 8];
}

#define MMA_TF32(d, a, b0, b1) \
    asm volatile("mma.sync.aligned.m16n8k8.row.col.f32.tf32.tf32.f32 " \
        "{%0,%1,%2,%3}, {%4,%5,%6,%7}, {%8,%9}, {%0,%1,%2,%3};" \
        : "+f"((d)[0]), "+f"((d)[1]), "+f"((d)[2]), "+f"((d)[3]) \
        : "r"((a).x), "r"((a).y), "r"((a).z), "r"((a).w), "r"(b0), "r"(b1))

// ---------------- offset conv via 3xTF32 mma.sync ----------------
#define OSSP 68
#define OFF_SROW_F (16 * 3 * 64)
#define OFF_SMEM ((OFF_SROW_F + 144 * OSSP) * 4)
__global__ void __launch_bounds__(256) offset_conv_kernel(const float* __restrict__ x,
                                                          const float* __restrict__ off_b) {
    extern __shared__ __align__(16) float osm[];
    float* srow = osm;
    float* ssam = osm + OFF_SROW_F;

    int bh = blockIdx.x;
    int b = bh >> 6, h = bh & 63;
    int tid = threadIdx.x;
    int lane = tid & 31, wid = tid >> 5;
    int wr = wid >> 2;
    int ng = wid & 3;
    int g = lane >> 2, tig = lane & 3;

    float d[2][4];
#pragma unroll
    for (int i = 0; i < 2; i++)
#pragma unroll
        for (int j = 0; j < 4; j++) d[i][j] = 0.f;

    unsigned sbase = (unsigned)__cvta_generic_to_shared(ssam);

#pragma unroll 1
    for (int cb = 0; cb < 16; cb++) {
        for (int e = tid; e < 768; e += 256) {
            int c  = e / 48;
            int rr = (e / 16) % 3;
            int f4 = e % 16;
            int row = h + rr - 1;
            float4 v = make_float4(0.f, 0.f, 0.f, 0.f);
            if ((unsigned)row < 64u)
                v = *(const float4*)(x + ((size_t)(b * CIN + cb * 16 + c)) * HW + row * 64 + f4 * 4);
            *(float4*)&srow[(c * 3 + rr) * 64 + f4 * 4] = v;
        }
        __syncthreads();
        for (int e = tid; e < 9216; e += 256) {
            int ck = e >> 6, p = e & 63;
            int c = ck / 9, tap = ck - c * 9;
            int col = p + (tap % 3) - 1;
            float v = ((unsigned)col < 64u) ? srow[(c * 3 + tap / 3) * 64 + col] : 0.f;
            ssam[ck * OSSP + p] = v;
        }
        __syncthreads();
        const uint4* ph = g_wOhi + (cb * 18 * 2 + wr) * 32 + lane;
        const uint4* pl = g_wOlo + (cb * 18 * 2 + wr) * 32 + lane;
#pragma unroll 2
        for (int kc = 0; kc < 18; kc++) {
            uint4 ah = __ldg(ph + kc * 64);
            uint4 al = __ldg(pl + kc * 64);
            unsigned base0 = sbase + ((kc * 8 + tig) * OSSP + ng * 16 + g) * 4;
            unsigned base1 = base0 + 4 * OSSP * 4;
#pragma unroll
            for (int nt = 0; nt < 2; nt++) {
                float s0, s1;
                asm volatile("ld.shared.f32 %0, [%1];" : "=f"(s0) : "r"(base0 + nt * 32));
                asm volatile("ld.shared.f32 %0, [%1];" : "=f"(s1) : "r"(base1 + nt * 32));
                unsigned bh0 = f2tf(s0), bh1 = f2tf(s1);
                unsigned bl0 = f2tf(s0 - __uint_as_float(bh0));
                unsigned bl1 = f2tf(s1 - __uint_as_float(bh1));
                MMA_TF32(d[nt], ah, bh0, bh1);
                MMA_TF32(d[nt], al, bh0, bh1);
                MMA_TF32(d[nt], ah, bl0, bl1);
            }
        }
        __syncthreads();
    }

    int m0 = wr * 16 + g;
    int m1 = m0 + 8;
    float b0v = (m0 < 27) ? off_b[m0] : 0.f;
    float b1v = (m1 < 27) ? off_b[m1] : 0.f;
#pragma unroll
    for (int nt = 0; nt < 2; nt++) {
        int p = ng * 16 + nt * 8 + 2 * tig;
        float v0 = d[nt][0] + b0v, v1 = d[nt][1] + b0v;
        float v2 = d[nt][2] + b1v, v3 = d[nt][3] + b1v;
        if (m0 >= 18) { v0 = 1.f / (1.f + __expf(-v0)); v1 = 1.f / (1.f + __expf(-v1)); }
        if (m1 >= 18) { v2 = 1.f / (1.f + __expf(-v2)); v3 = 1.f / (1.f + __expf(-v3)); }
        if (m0 < 27) { g_off[b][m0][h * 64 + p] = v0; g_off[b][m0][h * 64 + p + 1] = v1; }
        if (m1 < 27) { g_off[b][m1][h * 64 + p] = v2; g_off[b][m1][h * 64 + p + 1] = v3; }
    }
}

// ---------------- deformable conv (db fp32 ssam; 4m x 2n warp tiling) -------
#define SSP2 36
__device__ __forceinline__ void dgather(int tid, int cb, float* sbuf,
                                        const float* __restrict__ xtb,
                                        const ushort4* sidx, const float4* swt) {
    for (int it = tid; it < 1152; it += 256) {
        int c = it & 15;
        int kp = it >> 4;
        int k = kp >> 3;
        int p4 = kp & 7;
        const float* xc = xtb + cb * 16 + c;
        float4 v;
        float* vp = &v.x;
#pragma unroll
        for (int j = 0; j < 4; j++) {
            int e = k * 32 + p4 * 4 + j;
            ushort4 id = sidx[e];
            float4 wt = swt[e];
            float r =      wt.x * __ldg(xc + (int)id.x * CIN);
            r = fmaf(wt.y, __ldg(xc + (int)id.y * CIN), r);
            r = fmaf(wt.z, __ldg(xc + (int)id.z * CIN), r);
            r = fmaf(wt.w, __ldg(xc + (int)id.w * CIN), r);
            vp[j] = r;
        }
        *(float4*)&sbuf[(k * 16 + c) * SSP2 + p4 * 4] = v;
    }
}

__global__ void __launch_bounds__(256) deform_kernel(const float* __restrict__ dcn_b) {
    int blk = blockIdx.x;
    int b = blk >> 7;
    int t = blk & 127;
    int h = t >> 1;
    int w0 = (t & 1) << 5;
    int p0 = h * 64 + w0;
    int tid = threadIdx.x;
    int lane = tid & 31, wid = tid >> 5;

    __shared__ ushort4 sidx[288];
    __shared__ float4  swt[288];
    __shared__ __align__(16) float ssam[2][144 * SSP2];

    for (int e = tid; e < 288; e += 256) {
        int k = e >> 5, p = e & 31;
        float dy = g_off[b][k][p0 + p];
        float dx = g_off[b][9 + k][p0 + p];
        float m  = g_off[b][18 + k][p0 + p];
        float py = dy + (float)(k / 3 - 1 + h);
        float px = dx + (float)(k % 3 - 1 + w0 + p);
        float y0f = floorf(py), x0f = floorf(px);
        int y0 = (int)y0f, x0i = (int)x0f;
        float wy = py - y0f, wx = px - x0f;
        float w00 = (1.f - wy) * (1.f - wx) * m;
        float w01 = (1.f - wy) * wx * m;
        float w10 = wy * (1.f - wx) * m;
        float w11 = wy * wx * m;
        int y1 = y0 + 1, x1i = x0i + 1;
        bool y0v = (unsigned)y0  < 64u, y1v = (unsigned)y1  < 64u;
        bool x0v = (unsigned)x0i < 64u, x1v = (unsigned)x1i < 64u;
        int y0c = min(max(y0, 0), 63),  y1c = min(max(y1, 0), 63);
        int x0c = min(max(x0i, 0), 63), x1c = min(max(x1i, 0), 63);
        sidx[e] = make_ushort4((unsigned short)(y0c * 64 + x0c),
                               (unsigned short)(y0c * 64 + x1c),
                               (unsigned short)(y1c * 64 + x0c),
                               (unsigned short)(y1c * 64 + x1c));
        swt[e] = make_float4(y0v && x0v ? w00 : 0.f,
                             y0v && x1v ? w01 : 0.f,
                             y1v && x0v ? w10 : 0.f,
                             y1v && x1v ? w11 : 0.f);
    }
    __syncthreads();

    int g   = lane >> 2;
    int tig = lane & 3;
    int mq  = wid & 3;       // m-quarter: m-frags mq*2, mq*2+1
    int ngh = wid >> 2;      // n-half: px 16*ngh .. 16*ngh+15

    float d[2][2][4];        // [mf][ntl][4]
#pragma unroll
    for (int i = 0; i < 2; i++)
#pragma unroll
        for (int j = 0; j < 2; j++)
#pragma unroll
            for (int q = 0; q < 4; q++) d[i][j][q] = 0.f;

    unsigned sbase = (unsigned)__cvta_generic_to_shared(&ssam[0][0]) + (ngh * 16) * 4;
    const float* xtb = g_xt + (size_t)b * HW * CIN;

    dgather(tid, 0, &ssam[0][0], xtb, sidx, swt);
    __syncthreads();

#pragma unroll 1
    for (int cb = 0; cb < 16; cb++) {
        if (cb < 15) dgather(tid, cb + 1, &ssam[(cb + 1) & 1][0], xtb, sidx, swt);
        const uint4* ph = g_wAhi + ((cb * 18) * 8 + mq * 2) * 32 + lane;
        const uint4* pl = g_wAlo + ((cb * 18) * 8 + mq * 2) * 32 + lane;
        unsigned sb = sbase + (cb & 1) * (144 * SSP2 * 4);
#pragma unroll 2
        for (int kc = 0; kc < 18; kc++) {
            uint4 ah0 = __ldg(ph + kc * 256);
            uint4 ah1 = __ldg(ph + kc * 256 + 32);
            uint4 al0 = __ldg(pl + kc * 256);
            uint4 al1 = __ldg(pl + kc * 256 + 32);
            unsigned base0 = sb + ((kc * 8 + tig) * SSP2 + g) * 4;
            unsigned base1 = base0 + 4 * SSP2 * 4;
#pragma unroll
            for (int ntl = 0; ntl < 2; ntl++) {
                float s0, s1;
                asm volatile("ld.shared.f32 %0, [%1];" : "=f"(s0) : "r"(base0 + ntl * 32));
                asm volatile("ld.shared.f32 %0, [%1];" : "=f"(s1) : "r"(base1 + ntl * 32));
                unsigned bh0 = f2tf(s0), bh1 = f2tf(s1);
                unsigned bl0 = f2tf(s0 - __uint_as_float(bh0));
                unsigned bl1 = f2tf(s1 - __uint_as_float(bh1));
                MMA_TF32(d[0][ntl], ah0, bh0, bh1);
                MMA_TF32(d[0][ntl], al0, bh0, bh1);
                MMA_TF32(d[0][ntl], ah0, bl0, bl1);
                MMA_TF32(d[1][ntl], ah1, bh0, bh1);
                MMA_TF32(d[1][ntl], al1, bh0, bh1);
                MMA_TF32(d[1][ntl], ah1, bl0, bl1);
            }
        }
        __syncthreads();
    }

#pragma unroll
    for (int mf = 0; mf < 2; mf++) {
        int oc0 = (mq * 2 + mf) * 16 + g;
        float bias0 = dcn_b[oc0], bias1 = dcn_b[oc0 + 8];
        float* r0 = &g_out1[b][oc0][p0];
        float* r1 = &g_out1[b][oc0 + 8][p0];
#pragma unroll
        for (int ntl = 0; ntl < 2; ntl++) {
            int col = ngh * 16 + ntl * 8 + 2 * tig;
            *(float2*)(r0 + col) = make_float2(d[mf][ntl][0] + bias0, d[mf][ntl][1] + bias0);
            *(float2*)(r1 + col) = make_float2(d[mf][ntl][2] + bias1, d[mf][ntl][3] + bias1);
        }
    }
}

// ---------------- BN stats ----------------
__global__ void bn_partial_kernel(const float* __restrict__ ext, int which) {
    int bx = blockIdx.x;
    int c = bx >> 2, b = bx & 3;
    const float* plane = which ? ext + (size_t)(b * 128 + c) * 16384
                               : &g_out1[b][c][0];
    int n4 = which ? 4096 : 1024;
    float s = 0.f, s2 = 0.f;
    const float4* p4 = (const float4*)plane;
    for (int i = threadIdx.x; i < n4; i += 128) {
        float4 v = p4[i];
        s  += v.x + v.y + v.z + v.w;
        s2 += v.x*v.x + v.y*v.y + v.z*v.z + v.w*v.w;
    }
    __shared__ float rs[128], rq[128];
    rs[threadIdx.x] = s; rq[threadIdx.x] = s2;
    __syncthreads();
    for (int st = 64; st > 0; st >>= 1) {
        if (threadIdx.x < st) {
            rs[threadIdx.x] += rs[threadIdx.x + st];
            rq[threadIdx.x] += rq[threadIdx.x + st];
        }
        __syncthreads();
    }
    if (threadIdx.x == 0) {
        g_psum[which][bx][0] = rs[0];
        g_psum[which][bx][1] = rq[0];
    }
}

__global__ void bn_final_kernel(const float* __restrict__ gamma,
                                const float* __restrict__ beta, int which) {
    int c = threadIdx.x;
    float s = 0.f, s2 = 0.f;
#pragma unroll
    for (int b = 0; b < 4; b++) {
        s  += g_psum[which][c * 4 + b][0];
        s2 += g_psum[which][c * 4 + b][1];
    }
    float n  = which ? 65536.f : 16384.f;
    float mu = s / n;
    float var = s2 / n - mu * mu;
    float sc = gamma[c] * rsqrtf(var + 1e-5f);
    float sh = beta[c] - mu * sc;
    if (which == 0) { g_bn1s[c] = sc; g_bn1b[c] = sh; }
    else            { g_bn2s[c] = sc; g_bn2b[c] = sh; }
}

// ---------------- transposed conv via 3xTF32 mma.sync (u2 hi/lo ssam) -------
#define SSP 68
__global__ void __launch_bounds__(256) transp_kernel(float* __restrict__ out) {
    int blk = blockIdx.x;
    int u   = blk & 63;
    int par = (blk >> 6) & 3;
    int b   = blk >> 8;
    int py = par >> 1, px = par & 1;
    int tid = threadIdx.x;
    int lane = tid & 31, wid = tid >> 5;

    __shared__ float srow[16 * 2 * 64];
    __shared__ __align__(16) uint2 ssam[64 * SSP];

    int g = lane >> 2, tig = lane & 3;

    float d[8][4];
#pragma unroll
    for (int i = 0; i < 8; i++)
#pragma unroll
        for (int j = 0; j < 4; j++) d[i][j] = 0.f;

    unsigned sbase = (unsigned)__cvta_generic_to_shared(ssam);

#pragma unroll 1
    for (int cb = 0; cb < 8; cb++) {
        for (int e = tid; e < 512; e += 256) {
            int ci = e >> 5;
            int tt = (e >> 4) & 1;
            int f4 = e & 15;
            int c  = cb * 16 + ci;
            int row = u + py - 1 + tt;
            float4 v = make_float4(0.f, 0.f, 0.f, 0.f);
            if ((unsigned)row < 64u) {
                float4 r = *(const float4*)&g_out1[b][c][row * 64 + f4 * 4];
                float sc = g_bn1s[c], sh = g_bn1b[c];
                v.x = fmaxf(fmaf(r.x, sc, sh), 0.f);
                v.y = fmaxf(fmaf(r.y, sc, sh), 0.f);
                v.z = fmaxf(fmaf(r.z, sc, sh), 0.f);
                v.w = fmaxf(fmaf(r.w, sc, sh), 0.f);
            }
            *(float4*)&srow[(ci * 2 + tt) * 64 + f4 * 4] = v;
        }
        __syncthreads();
        for (int e = tid; e < 4096; e += 256) {
            int ck = e >> 6;
            int p  = e & 63;
            int ci = ck >> 2;
            int tt = (ck >> 1) & 1;
            int s  = ck & 1;
            int col = p + px - 1 + s;
            float v = (col >= 0 && col < 64) ? srow[(ci * 2 + tt) * 64 + col] : 0.f;
            unsigned hi = f2tf(v);
            unsigned lo = f2tf(v - __uint_as_float(hi));
            ssam[ck * SSP + p] = make_uint2(hi, lo);
        }
        __syncthreads();
        const uint4* ph = g_wBhi + (((par * 8 + cb) * 8) * 8 + wid) * 32 + lane;
        const uint4* pl = g_wBlo + (((par * 8 + cb) * 8) * 8 + wid) * 32 + lane;
#pragma unroll 2
        for (int kc = 0; kc < 8; kc++) {
            uint4 ah = __ldg(ph + kc * 256);
            uint4 al = __ldg(pl + kc * 256);
            unsigned base0 = sbase + ((kc * 8 + tig) * SSP + g) * 8;
            unsigned base1 = base0 + 4 * SSP * 8;
#pragma unroll
            for (int nt = 0; nt < 8; nt++) {
                unsigned h0, l0, h1, l1;
                asm volatile("ld.shared.v2.u32 {%0,%1}, [%2];"
                             : "=r"(h0), "=r"(l0) : "r"(base0 + nt * 64));
                asm volatile("ld.shared.v2.u32 {%0,%1}, [%2];"
                             : "=r"(h1), "=r"(l1) : "r"(base1 + nt * 64));
                MMA_TF32(d[nt], ah, h0, h1);
                MMA_TF32(d[nt], al, h0, h1);
                MMA_TF32(d[nt], ah, l0, l1);
            }
        }
        __syncthreads();
    }

    int y = 2 * u + py;
    int oc0 = wid * 16 + g;
    float* r0 = out + (((size_t)(b * 128 + oc0)     * 128 + y) * 128) + px;
    float* r1 = out + (((size_t)(b * 128 + oc0 + 8) * 128 + y) * 128) + px;
#pragma unroll
    for (int nt = 0; nt < 8; nt++) {
        int p = nt * 8 + 2 * tig;
        r0[2 * p]       = d[nt][0];
        r0[2 * (p + 1)] = d[nt][1];
        r1[2 * p]       = d[nt][2];
        r1[2 * (p + 1)] = d[nt][3];
    }
}

// ---------------- BN2 apply + ReLU ----------------
__global__ void bn_apply_kernel(float* __restrict__ out) {
    int i = blockIdx.x * 256 + threadIdx.x;
    int c = (i >> 12) & 127;
    float sc = g_bn2s[c], sh = g_bn2b[c];
    float4 v = ((float4*)out)[i];
    v.x = fmaxf(v.x * sc + sh, 0.f);
    v.y = fmaxf(v.y * sc + sh, 0.f);
    v.z = fmaxf(v.z * sc + sh, 0.f);
    v.w = fmaxf(v.w * sc + sh, 0.f);
    ((float4*)out)[i] = v;
}

// ---------------- launch ----------------
extern "C" void kernel_launch(void* const* d_in, const int* in_sizes, int n_in,
                              void* d_out, int out_size) {
    const float* x     = (const float*)d_in[0];
    const float* off_w = (const float*)d_in[1];
    const float* off_b = (const float*)d_in[2];
    const float* dcn_w = (const float*)d_in[3];
    const float* dcn_b = (const float*)d_in[4];
    const float* bn1_g = (const float*)d_in[5];
    const float* bn1_b = (const float*)d_in[6];
    const float* up_w  = (const float*)d_in[7];
    const float* bn2_g = (const float*)d_in[8];
    const float* bn2_b = (const float*)d_in[9];
    float* out = (float*)d_out;

    cudaFuncSetAttribute(deform_kernel,
                         cudaFuncAttributePreferredSharedMemoryCarveout, 100);
    cudaFuncSetAttribute(transp_kernel,
                         cudaFuncAttributePreferredSharedMemoryCarveout, 100);
    cudaFuncSetAttribute(offset_conv_kernel,
                         cudaFuncAttributeMaxDynamicSharedMemorySize, OFF_SMEM);
    cudaFuncSetAttribute(offset_conv_kernel,
                         cudaFuncAttributePreferredSharedMemoryCarveout, 100);

    prep_kernel<<<288, 256>>>(dcn_w, up_w, off_w);
    nhwc_kernel<<<dim3(128, 8, 4), dim3(32, 8)>>>(x);
    offset_conv_kernel<<<256, 256, OFF_SMEM>>>(x, off_b);
    deform_kernel<<<512, 256>>>(dcn_b);
    bn_partial_kernel<<<512, 128>>>(nullptr, 0);
    bn_final_kernel<<<1, 128>>>(bn1_g, bn1_b, 0);
    transp_kernel<<<1024, 256>>>(out);
    bn_partial_kernel<<<512, 128>>>(out, 1);
    bn_final_kernel<<<1, 128>>>(bn2_g, bn2_b, 1);
    bn_apply_kernel<<<8192, 256>>>(out);
}